// round 1
// baseline (speedup 1.0000x reference)
#include <cuda_runtime.h>
#include <math.h>
#include <math_constants.h>

// Problem dims
#define Nn 16
#define Ss 64
#define Hh 256
#define FAa 256
#define Bb (Nn*Ss)              // 1024 chains / rows
#define NM_ELEMS (Nn*Ss*Hh)     // 262144
#define ATTN_ELEMS (Nn*Ss*Ss)   // 65536

// Scratch (device globals: no allocation allowed)
__device__ float g_G [Bb*Ss];   // gate logits (n,i,j)
__device__ float g_A1[Bb*Hh];   // facts@Wr^T + Wr_b + Ur_b   (row = n*64 + t)
__device__ float g_A2[Bb*Hh];   // facts@W^T  + W_b
__device__ float g_Ca[Bb*Hh];
__device__ float g_Cb[Bb*Hh];

// ---------------------------------------------------------------------------
// Zero initial GRU state
// ---------------------------------------------------------------------------
__global__ void zero_kernel() {
    g_Ca[blockIdx.x * 512 + threadIdx.x] = 0.0f;
}

// ---------------------------------------------------------------------------
// Gate MLP: per CTA = one (n,i). Computes T[j,a] = sum_k Z[j,k]*z1w[a,k],
// then G[j] = sum_a tanh(T+b1)*z2w + z2b.
// Z built on the fly: block0 f*q, block1 f*m, block2 |f-q|, block3 |f-m|.
// ---------------------------------------------------------------------------
#define SF_PITCH 257
#define SA_PITCH 68
#define SW_PITCH 260
#define GATE_SMEM_FLOATS (64*SF_PITCH + 4*256 + 32*SA_PITCH + 32*SW_PITCH)

__global__ void __launch_bounds__(256, 2)
gate_kernel(const float* __restrict__ facts,
            const float* __restrict__ prevM,
            const float* __restrict__ questions,
            const float* __restrict__ z1w,
            const float* __restrict__ z1b,
            const float* __restrict__ z2w,
            const float* __restrict__ z2b)
{
    extern __shared__ float smem[];
    float* sf  = smem;                 // 64 x 257   facts rows for this n
    float* sq  = sf  + 64*SF_PITCH;    // 256
    float* smm = sq  + 256;            // 256
    float* sb1 = smm + 256;            // 256
    float* sz2 = sb1 + 256;            // 256
    float* sA  = sz2 + 256;            // 32 x 68  (k-major A tile)
    float* sW  = sA  + 32*SA_PITCH;    // 32 x 260 (k-major W tile)

    const int tid = threadIdx.x;
    const int ni  = blockIdx.x;        // n*64 + i
    const int n   = ni >> 6;

    const float* frow = facts + (size_t)n * Ss * Hh;
    const float* qrow = questions + (size_t)ni * Hh;
    const float* mrow = prevM + (size_t)ni * Hh;

    for (int idx = tid; idx < Ss*Hh; idx += 256) {
        int j = idx >> 8, h = idx & 255;
        sf[j*SF_PITCH + h] = frow[idx];
    }
    sq [tid] = qrow[tid];
    smm[tid] = mrow[tid];
    sb1[tid] = z1b[tid];
    sz2[tid] = z2w[tid];
    __syncthreads();

    const int tj = tid & 15;           // j group
    const int ta = tid >> 4;           // a group
    const int j0 = tj * 4;
    const int a0 = ta * 16;

    float acc[4][16];
    #pragma unroll
    for (int jj = 0; jj < 4; jj++)
        #pragma unroll
        for (int aa = 0; aa < 16; aa++) acc[jj][aa] = 0.0f;

    for (int b = 0; b < 4; b++) {
        const float* tv = (b == 0 || b == 2) ? sq : smm;
        const bool isabs = (b >= 2);
        for (int h0 = 0; h0 < 256; h0 += 32) {
            __syncthreads();
            // Build A tile: sA[k][j] = op(f[j,h0+k], t[h0+k])
            #pragma unroll
            for (int e = 0; e < 8; e++) {
                int idx = e*256 + tid;
                int k = idx >> 6, j = idx & 63;
                float f = sf[j*SF_PITCH + h0 + k];
                float t = tv[h0 + k];
                sA[k*SA_PITCH + j] = isabs ? fabsf(f - t) : f * t;
            }
            // Load W tile: sW[k][a] = z1w[a, b*256 + h0 + k]  (coalesced over k)
            #pragma unroll
            for (int r = 0; r < 32; r++) {
                int idx = r*256 + tid;
                int a = idx >> 5, k = idx & 31;
                sW[k*SW_PITCH + a] = z1w[(size_t)a*1024 + b*256 + h0 + k];
            }
            __syncthreads();
            #pragma unroll 4
            for (int k = 0; k < 32; k++) {
                float4 av = *(const float4*)&sA[k*SA_PITCH + j0];
                const float* wrow = &sW[k*SW_PITCH + a0];
                #pragma unroll
                for (int q = 0; q < 4; q++) {
                    float4 wv = *(const float4*)&wrow[q*4];
                    acc[0][q*4+0] += av.x * wv.x; acc[0][q*4+1] += av.x * wv.y;
                    acc[0][q*4+2] += av.x * wv.z; acc[0][q*4+3] += av.x * wv.w;
                    acc[1][q*4+0] += av.y * wv.x; acc[1][q*4+1] += av.y * wv.y;
                    acc[1][q*4+2] += av.y * wv.z; acc[1][q*4+3] += av.y * wv.w;
                    acc[2][q*4+0] += av.z * wv.x; acc[2][q*4+1] += av.z * wv.y;
                    acc[2][q*4+2] += av.z * wv.z; acc[2][q*4+3] += av.z * wv.w;
                    acc[3][q*4+0] += av.w * wv.x; acc[3][q*4+1] += av.w * wv.y;
                    acc[3][q*4+2] += av.w * wv.z; acc[3][q*4+3] += av.w * wv.w;
                }
            }
        }
    }

    // Epilogue: tanh + z2 dot, reduce over the 16 a-groups
    float zb = z2b[0];
    float part[4];
    #pragma unroll
    for (int jj = 0; jj < 4; jj++) {
        float p = 0.0f;
        #pragma unroll
        for (int aa = 0; aa < 16; aa++)
            p += tanhf(acc[jj][aa] + sb1[a0+aa]) * sz2[a0+aa];
        part[jj] = p;
    }
    __syncthreads();               // done reading sA; reuse as reduction buffer
    float* red = sA;               // 64 x 16
    #pragma unroll
    for (int jj = 0; jj < 4; jj++) red[(j0+jj)*16 + ta] = part[jj];
    __syncthreads();
    if (tid < 64) {
        float g = zb;
        #pragma unroll
        for (int t2 = 0; t2 < 16; t2++) g += red[tid*16 + t2];
        g_G[ni*64 + tid] = g;
    }
}

// ---------------------------------------------------------------------------
// Masked softmax over facts axis j. One warp per (n,i) row.
// Gm = G*mask; Gm==0 -> -inf (replicates reference exactly).
// ---------------------------------------------------------------------------
__global__ void softmax_kernel(const int* __restrict__ doc_len,
                               float* __restrict__ out_attn)
{
    int row  = blockIdx.x * 4 + (threadIdx.x >> 5);
    int lane = threadIdx.x & 31;
    int n  = row >> 6;
    int dl = doc_len[n];

    float v0 = g_G[row*64 + lane];
    float v1 = g_G[row*64 + 32 + lane];
    float x0 = (lane      < dl && v0 != 0.0f) ? v0 : -CUDART_INF_F;
    float x1 = (lane + 32 < dl && v1 != 0.0f) ? v1 : -CUDART_INF_F;

    float mx = fmaxf(x0, x1);
    #pragma unroll
    for (int o = 16; o >= 1; o >>= 1)
        mx = fmaxf(mx, __shfl_xor_sync(0xffffffffu, mx, o));

    float e0 = expf(x0 - mx);
    float e1 = expf(x1 - mx);
    float s = e0 + e1;
    #pragma unroll
    for (int o = 16; o >= 1; o >>= 1)
        s += __shfl_xor_sync(0xffffffffu, s, o);

    float inv = 1.0f / s;
    out_attn[row*64 + lane]      = e0 * inv;
    out_attn[row*64 + 32 + lane] = e1 * inv;
}

// ---------------------------------------------------------------------------
// A1 = facts@Wr^T + Wr_b + Ur_b ; A2 = facts@W^T + W_b
// blockIdx.y < 4 -> A1 o-tile, else A2 o-tile. Tiles 64 rows x 64 outs.
// ---------------------------------------------------------------------------
__global__ void a12_kernel(const float* __restrict__ facts,
                           const float* __restrict__ Wr, const float* __restrict__ Wrb,
                           const float* __restrict__ Urb,
                           const float* __restrict__ W,  const float* __restrict__ Wb)
{
    __shared__ float sX[64*68];
    __shared__ float sWm[64*68];
    const int rt = blockIdx.x;
    const int yy = blockIdx.y;
    const bool first = (yy < 4);
    const int ot = first ? yy : yy - 4;
    const float* Wm = first ? Wr : W;
    float* outp = first ? g_A1 : g_A2;

    const int tid = threadIdx.x;
    const int tr = tid & 15, to = tid >> 4;
    const int r0 = tr*4, o0 = to*4;
    float acc[4][4];
    #pragma unroll
    for (int a = 0; a < 4; a++)
        #pragma unroll
        for (int b = 0; b < 4; b++) acc[a][b] = 0.0f;

    for (int k0 = 0; k0 < 256; k0 += 64) {
        __syncthreads();
        #pragma unroll
        for (int e = 0; e < 16; e++) {
            int idx = e*256 + tid;
            int r = idx >> 6, k = idx & 63;
            sX[k*68 + r]  = facts[(size_t)(rt*64 + r)*256 + k0 + k];
            int o = r;
            sWm[k*68 + o] = Wm[(size_t)(ot*64 + o)*256 + k0 + k];
        }
        __syncthreads();
        #pragma unroll 4
        for (int k = 0; k < 64; k++) {
            float4 xv = *(const float4*)&sX[k*68 + r0];
            float4 wv = *(const float4*)&sWm[k*68 + o0];
            acc[0][0]+=xv.x*wv.x; acc[0][1]+=xv.x*wv.y; acc[0][2]+=xv.x*wv.z; acc[0][3]+=xv.x*wv.w;
            acc[1][0]+=xv.y*wv.x; acc[1][1]+=xv.y*wv.y; acc[1][2]+=xv.y*wv.z; acc[1][3]+=xv.y*wv.w;
            acc[2][0]+=xv.z*wv.x; acc[2][1]+=xv.z*wv.y; acc[2][2]+=xv.z*wv.z; acc[2][3]+=xv.z*wv.w;
            acc[3][0]+=xv.w*wv.x; acc[3][1]+=xv.w*wv.y; acc[3][2]+=xv.w*wv.z; acc[3][3]+=xv.w*wv.w;
        }
    }
    #pragma unroll
    for (int rr = 0; rr < 4; rr++)
        #pragma unroll
        for (int oo = 0; oo < 4; oo++) {
            int o = ot*64 + o0 + oo;
            float bias = first ? (Wrb[o] + Urb[o]) : Wb[o];
            outp[(size_t)(rt*64 + r0 + rr)*256 + o] = acc[rr][oo] + bias;
        }
}

// ---------------------------------------------------------------------------
// One GRU step (fused: 2 matvecs + sigmoid/tanh + convex update).
// Grid: 16 chain-tiles x 8 out-tiles. Tile: 64 chains x 32 outs.
// ---------------------------------------------------------------------------
__global__ void step_kernel(const float* __restrict__ Cin, float* __restrict__ Cout,
                            const float* __restrict__ Ur, const float* __restrict__ U,
                            const float* __restrict__ Ub,
                            const float* __restrict__ attn, int t)
{
    __shared__ float sC [64*68];   // k x chain
    __shared__ float sUr[64*34];   // k x out
    __shared__ float sU [64*34];
    const int ct = blockIdx.x;
    const int ot = blockIdx.y;
    const int tid = threadIdx.x;
    const int tc = tid & 15, to = tid >> 4;
    const int c0 = tc*4, o0 = to*2;

    float aU[4][2], aV[4][2];
    #pragma unroll
    for (int a = 0; a < 4; a++) { aU[a][0]=aU[a][1]=aV[a][0]=aV[a][1]=0.0f; }

    for (int k0 = 0; k0 < 256; k0 += 64) {
        __syncthreads();
        #pragma unroll
        for (int e = 0; e < 16; e++) {
            int idx = e*256 + tid;
            int c = idx >> 6, k = idx & 63;
            sC[k*68 + c] = Cin[(size_t)(ct*64 + c)*256 + k0 + k];
        }
        #pragma unroll
        for (int e = 0; e < 8; e++) {
            int idx = e*256 + tid;
            int o = idx >> 6, k = idx & 63;
            sUr[k*34 + o] = Ur[(size_t)(ot*32 + o)*256 + k0 + k];
            sU [k*34 + o] = U [(size_t)(ot*32 + o)*256 + k0 + k];
        }
        __syncthreads();
        #pragma unroll 4
        for (int k = 0; k < 64; k++) {
            float4 cv  = *(const float4*)&sC [k*68 + c0];
            float2 urv = *(const float2*)&sUr[k*34 + o0];
            float2 uv  = *(const float2*)&sU [k*34 + o0];
            aU[0][0]+=cv.x*urv.x; aU[0][1]+=cv.x*urv.y; aV[0][0]+=cv.x*uv.x; aV[0][1]+=cv.x*uv.y;
            aU[1][0]+=cv.y*urv.x; aU[1][1]+=cv.y*urv.y; aV[1][0]+=cv.y*uv.x; aV[1][1]+=cv.y*uv.y;
            aU[2][0]+=cv.z*urv.x; aU[2][1]+=cv.z*urv.y; aV[2][0]+=cv.z*uv.x; aV[2][1]+=cv.z*uv.y;
            aU[3][0]+=cv.w*urv.x; aU[3][1]+=cv.w*urv.y; aV[3][0]+=cv.w*uv.x; aV[3][1]+=cv.w*uv.y;
        }
    }

    #pragma unroll
    for (int cc = 0; cc < 4; cc++) {
        int b = ct*64 + c0 + cc;
        int n = b >> 6;
        float g = attn[b*64 + t];
        #pragma unroll
        for (int oo = 0; oo < 2; oo++) {
            int o = ot*32 + o0 + oo;
            float u = aU[cc][oo] + g_A1[(size_t)(n*64 + t)*256 + o];
            float v = aV[cc][oo] + Ub[o];
            float r = 1.0f / (1.0f + expf(-u));
            float h = tanhf(g_A2[(size_t)(n*64 + t)*256 + o] + r * v);
            float ci = Cin[(size_t)b*256 + o];
            Cout[(size_t)b*256 + o] = g*h + (1.0f - g)*ci;
        }
    }
}

// ---------------------------------------------------------------------------
// next_mem = relu([prevM, C, questions] @ nm_w^T + nm_b). Tiles 32 rows x 64 o.
// ---------------------------------------------------------------------------
__global__ void final_kernel(const float* __restrict__ prevM,
                             const float* __restrict__ questions,
                             const float* __restrict__ C,
                             const float* __restrict__ nmw,
                             const float* __restrict__ nmb,
                             float* __restrict__ out)
{
    __shared__ float sX[64*36];   // k x row (32 rows)
    __shared__ float sW[64*68];   // k x out (64 outs)
    const int rt = blockIdx.x;    // 32 tiles of 32 rows
    const int ot = blockIdx.y;    // 4 tiles of 64 outs
    const int tid = threadIdx.x;
    const int tr = tid & 7, to = tid >> 3;
    const int r0 = tr*4, o0 = to*2;

    float acc[4][2];
    #pragma unroll
    for (int a = 0; a < 4; a++) { acc[a][0]=acc[a][1]=0.0f; }

    for (int k0 = 0; k0 < 768; k0 += 64) {
        __syncthreads();
        #pragma unroll
        for (int e = 0; e < 8; e++) {
            int idx = e*256 + tid;
            int r = idx >> 6, k = idx & 63;
            int kg = k0 + k;
            const float* src; int off;
            if (kg < 256)      { src = prevM;     off = kg; }
            else if (kg < 512) { src = C;         off = kg - 256; }
            else               { src = questions; off = kg - 512; }
            sX[k*36 + r] = src[(size_t)(rt*32 + r)*256 + off];
        }
        #pragma unroll
        for (int e = 0; e < 16; e++) {
            int idx = e*256 + tid;
            int o = idx >> 6, k = idx & 63;
            sW[k*68 + o] = nmw[(size_t)(ot*64 + o)*768 + k0 + k];
        }
        __syncthreads();
        #pragma unroll 4
        for (int k = 0; k < 64; k++) {
            float4 xv = *(const float4*)&sX[k*36 + r0];
            float2 wv = *(const float2*)&sW[k*68 + o0];
            acc[0][0]+=xv.x*wv.x; acc[0][1]+=xv.x*wv.y;
            acc[1][0]+=xv.y*wv.x; acc[1][1]+=xv.y*wv.y;
            acc[2][0]+=xv.z*wv.x; acc[2][1]+=xv.z*wv.y;
            acc[3][0]+=xv.w*wv.x; acc[3][1]+=xv.w*wv.y;
        }
    }
    #pragma unroll
    for (int rr = 0; rr < 4; rr++)
        #pragma unroll
        for (int oo = 0; oo < 2; oo++) {
            int o = ot*64 + o0 + oo;
            float v = acc[rr][oo] + nmb[o];
            out[(size_t)(rt*32 + r0 + rr)*256 + o] = fmaxf(v, 0.0f);
        }
}

// ---------------------------------------------------------------------------
extern "C" void kernel_launch(void* const* d_in, const int* in_sizes, int n_in,
                              void* d_out, int out_size)
{
    const float* facts     = (const float*)d_in[0];
    const float* prevM     = (const float*)d_in[1];
    const float* questions = (const float*)d_in[2];
    const int*   doc_len   = (const int*)  d_in[3];
    const float* z1w = (const float*)d_in[4];
    const float* z1b = (const float*)d_in[5];
    const float* z2w = (const float*)d_in[6];
    const float* z2b = (const float*)d_in[7];
    const float* Wrw = (const float*)d_in[8];
    const float* Wrb = (const float*)d_in[9];
    const float* Urw = (const float*)d_in[10];
    const float* Urb = (const float*)d_in[11];
    const float* Ww  = (const float*)d_in[12];
    const float* Wb  = (const float*)d_in[13];
    const float* Uw  = (const float*)d_in[14];
    const float* Ub  = (const float*)d_in[15];
    const float* nmw = (const float*)d_in[16];
    const float* nmb = (const float*)d_in[17];

    float* out      = (float*)d_out;              // next_mem first
    float* out_attn = out + NM_ELEMS;             // attn second

    const int gate_smem = GATE_SMEM_FLOATS * 4;
    cudaFuncSetAttribute(gate_kernel,
                         cudaFuncAttributeMaxDynamicSharedMemorySize, gate_smem);

    float *Ca, *Cb;
    cudaGetSymbolAddress((void**)&Ca, g_Ca);
    cudaGetSymbolAddress((void**)&Cb, g_Cb);

    zero_kernel<<<512, 512>>>();
    gate_kernel<<<1024, 256, gate_smem>>>(facts, prevM, questions, z1w, z1b, z2w, z2b);
    softmax_kernel<<<256, 128>>>(doc_len, out_attn);
    a12_kernel<<<dim3(16, 8), 256>>>(facts, Wrw, Wrb, Urb, Ww, Wb);

    for (int t = 0; t < 64; t++) {
        const float* cin = (t & 1) ? Cb : Ca;
        float*       cout = (t & 1) ? Ca : Cb;
        step_kernel<<<dim3(16, 8), 256>>>(cin, cout, Urw, Uw, Ub, out_attn, t);
    }
    // After t=63 (odd), final C lives in Ca
    final_kernel<<<dim3(32, 4), 256>>>(prevM, questions, Ca, nmw, nmb, out);
}

// round 2
// speedup vs baseline: 1.9522x; 1.9522x over previous
#include <cuda_runtime.h>
#include <math.h>
#include <math_constants.h>

// Problem dims
#define Nn 16
#define Ss 64
#define Hh 256
#define FAa 256
#define Bb (Nn*Ss)              // 1024 chains / rows
#define NM_ELEMS (Nn*Ss*Hh)     // 262144
#define ATTN_ELEMS (Nn*Ss*Ss)   // 65536

// Scratch (device globals: no allocation allowed)
__device__ float g_G [Bb*Ss];   // gate logits (n,i,j)
__device__ float g_A1[Bb*Hh];   // facts@Wr^T + Wr_b + Ur_b   (row = n*64 + t)
__device__ float g_A2[Bb*Hh];   // facts@W^T  + W_b
__device__ float g_Ca[Bb*Hh];
__device__ float g_Cb[Bb*Hh];

// Grid barrier state for the persistent GRU kernel
__device__ unsigned g_bar_count;
__device__ unsigned g_bar_gen;

// ---------------------------------------------------------------------------
// Zero initial GRU state + reset barrier
// ---------------------------------------------------------------------------
__global__ void zero_kernel() {
    int i = blockIdx.x * 512 + threadIdx.x;
    g_Ca[i] = 0.0f;
    if (i == 0) { g_bar_count = 0; g_bar_gen = 0; }
}

// ---------------------------------------------------------------------------
// Gate MLP: per CTA = one (n,i). Computes T[j,a] = sum_k Z[j,k]*z1w[a,k],
// then G[j] = sum_a tanh(T+b1)*z2w + z2b.
// ---------------------------------------------------------------------------
#define SF_PITCH 257
#define SA_PITCH 68
#define SW_PITCH 260
#define GATE_SMEM_FLOATS (64*SF_PITCH + 4*256 + 32*SA_PITCH + 32*SW_PITCH)

__global__ void __launch_bounds__(256, 2)
gate_kernel(const float* __restrict__ facts,
            const float* __restrict__ prevM,
            const float* __restrict__ questions,
            const float* __restrict__ z1w,
            const float* __restrict__ z1b,
            const float* __restrict__ z2w,
            const float* __restrict__ z2b)
{
    extern __shared__ float smem[];
    float* sf  = smem;                 // 64 x 257   facts rows for this n
    float* sq  = sf  + 64*SF_PITCH;    // 256
    float* smm = sq  + 256;            // 256
    float* sb1 = smm + 256;            // 256
    float* sz2 = sb1 + 256;            // 256
    float* sA  = sz2 + 256;            // 32 x 68  (k-major A tile)
    float* sW  = sA  + 32*SA_PITCH;    // 32 x 260 (k-major W tile)

    const int tid = threadIdx.x;
    const int ni  = blockIdx.x;        // n*64 + i
    const int n   = ni >> 6;

    const float* frow = facts + (size_t)n * Ss * Hh;
    const float* qrow = questions + (size_t)ni * Hh;
    const float* mrow = prevM + (size_t)ni * Hh;

    for (int idx = tid; idx < Ss*Hh; idx += 256) {
        int j = idx >> 8, h = idx & 255;
        sf[j*SF_PITCH + h] = frow[idx];
    }
    sq [tid] = qrow[tid];
    smm[tid] = mrow[tid];
    sb1[tid] = z1b[tid];
    sz2[tid] = z2w[tid];
    __syncthreads();

    const int tj = tid & 15;           // j group
    const int ta = tid >> 4;           // a group
    const int j0 = tj * 4;
    const int a0 = ta * 16;

    float acc[4][16];
    #pragma unroll
    for (int jj = 0; jj < 4; jj++)
        #pragma unroll
        for (int aa = 0; aa < 16; aa++) acc[jj][aa] = 0.0f;

    for (int b = 0; b < 4; b++) {
        const float* tv = (b == 0 || b == 2) ? sq : smm;
        const bool isabs = (b >= 2);
        for (int h0 = 0; h0 < 256; h0 += 32) {
            __syncthreads();
            #pragma unroll
            for (int e = 0; e < 8; e++) {
                int idx = e*256 + tid;
                int k = idx >> 6, j = idx & 63;
                float f = sf[j*SF_PITCH + h0 + k];
                float t = tv[h0 + k];
                sA[k*SA_PITCH + j] = isabs ? fabsf(f - t) : f * t;
            }
            #pragma unroll
            for (int r = 0; r < 32; r++) {
                int idx = r*256 + tid;
                int a = idx >> 5, k = idx & 31;
                sW[k*SW_PITCH + a] = z1w[(size_t)a*1024 + b*256 + h0 + k];
            }
            __syncthreads();
            #pragma unroll 4
            for (int k = 0; k < 32; k++) {
                float4 av = *(const float4*)&sA[k*SA_PITCH + j0];
                const float* wrow = &sW[k*SW_PITCH + a0];
                #pragma unroll
                for (int q = 0; q < 4; q++) {
                    float4 wv = *(const float4*)&wrow[q*4];
                    acc[0][q*4+0] += av.x * wv.x; acc[0][q*4+1] += av.x * wv.y;
                    acc[0][q*4+2] += av.x * wv.z; acc[0][q*4+3] += av.x * wv.w;
                    acc[1][q*4+0] += av.y * wv.x; acc[1][q*4+1] += av.y * wv.y;
                    acc[1][q*4+2] += av.y * wv.z; acc[1][q*4+3] += av.y * wv.w;
                    acc[2][q*4+0] += av.z * wv.x; acc[2][q*4+1] += av.z * wv.y;
                    acc[2][q*4+2] += av.z * wv.z; acc[2][q*4+3] += av.z * wv.w;
                    acc[3][q*4+0] += av.w * wv.x; acc[3][q*4+1] += av.w * wv.y;
                    acc[3][q*4+2] += av.w * wv.z; acc[3][q*4+3] += av.w * wv.w;
                }
            }
        }
    }

    float zb = z2b[0];
    float part[4];
    #pragma unroll
    for (int jj = 0; jj < 4; jj++) {
        float p = 0.0f;
        #pragma unroll
        for (int aa = 0; aa < 16; aa++)
            p += tanhf(acc[jj][aa] + sb1[a0+aa]) * sz2[a0+aa];
        part[jj] = p;
    }
    __syncthreads();
    float* red = sA;               // 64 x 16
    #pragma unroll
    for (int jj = 0; jj < 4; jj++) red[(j0+jj)*16 + ta] = part[jj];
    __syncthreads();
    if (tid < 64) {
        float g = zb;
        #pragma unroll
        for (int t2 = 0; t2 < 16; t2++) g += red[tid*16 + t2];
        g_G[ni*64 + tid] = g;
    }
}

// ---------------------------------------------------------------------------
// Masked softmax over facts axis j. One warp per (n,i) row.
// ---------------------------------------------------------------------------
__global__ void softmax_kernel(const int* __restrict__ doc_len,
                               float* __restrict__ out_attn)
{
    int row  = blockIdx.x * 4 + (threadIdx.x >> 5);
    int lane = threadIdx.x & 31;
    int n  = row >> 6;
    int dl = doc_len[n];

    float v0 = g_G[row*64 + lane];
    float v1 = g_G[row*64 + 32 + lane];
    float x0 = (lane      < dl && v0 != 0.0f) ? v0 : -CUDART_INF_F;
    float x1 = (lane + 32 < dl && v1 != 0.0f) ? v1 : -CUDART_INF_F;

    float mx = fmaxf(x0, x1);
    #pragma unroll
    for (int o = 16; o >= 1; o >>= 1)
        mx = fmaxf(mx, __shfl_xor_sync(0xffffffffu, mx, o));

    float e0 = expf(x0 - mx);
    float e1 = expf(x1 - mx);
    float s = e0 + e1;
    #pragma unroll
    for (int o = 16; o >= 1; o >>= 1)
        s += __shfl_xor_sync(0xffffffffu, s, o);

    float inv = 1.0f / s;
    out_attn[row*64 + lane]      = e0 * inv;
    out_attn[row*64 + 32 + lane] = e1 * inv;
}

// ---------------------------------------------------------------------------
// A1 = facts@Wr^T + Wr_b + Ur_b ; A2 = facts@W^T + W_b
// ---------------------------------------------------------------------------
__global__ void a12_kernel(const float* __restrict__ facts,
                           const float* __restrict__ Wr, const float* __restrict__ Wrb,
                           const float* __restrict__ Urb,
                           const float* __restrict__ W,  const float* __restrict__ Wb)
{
    __shared__ float sX[64*68];
    __shared__ float sWm[64*68];
    const int rt = blockIdx.x;
    const int yy = blockIdx.y;
    const bool first = (yy < 4);
    const int ot = first ? yy : yy - 4;
    const float* Wm = first ? Wr : W;
    float* outp = first ? g_A1 : g_A2;

    const int tid = threadIdx.x;
    const int tr = tid & 15, to = tid >> 4;
    const int r0 = tr*4, o0 = to*4;
    float acc[4][4];
    #pragma unroll
    for (int a = 0; a < 4; a++)
        #pragma unroll
        for (int b = 0; b < 4; b++) acc[a][b] = 0.0f;

    for (int k0 = 0; k0 < 256; k0 += 64) {
        __syncthreads();
        #pragma unroll
        for (int e = 0; e < 16; e++) {
            int idx = e*256 + tid;
            int r = idx >> 6, k = idx & 63;
            sX[k*68 + r]  = facts[(size_t)(rt*64 + r)*256 + k0 + k];
            int o = r;
            sWm[k*68 + o] = Wm[(size_t)(ot*64 + o)*256 + k0 + k];
        }
        __syncthreads();
        #pragma unroll 4
        for (int k = 0; k < 64; k++) {
            float4 xv = *(const float4*)&sX[k*68 + r0];
            float4 wv = *(const float4*)&sWm[k*68 + o0];
            acc[0][0]+=xv.x*wv.x; acc[0][1]+=xv.x*wv.y; acc[0][2]+=xv.x*wv.z; acc[0][3]+=xv.x*wv.w;
            acc[1][0]+=xv.y*wv.x; acc[1][1]+=xv.y*wv.y; acc[1][2]+=xv.y*wv.z; acc[1][3]+=xv.y*wv.w;
            acc[2][0]+=xv.z*wv.x; acc[2][1]+=xv.z*wv.y; acc[2][2]+=xv.z*wv.z; acc[2][3]+=xv.z*wv.w;
            acc[3][0]+=xv.w*wv.x; acc[3][1]+=xv.w*wv.y; acc[3][2]+=xv.w*wv.z; acc[3][3]+=xv.w*wv.w;
        }
    }
    #pragma unroll
    for (int rr = 0; rr < 4; rr++)
        #pragma unroll
        for (int oo = 0; oo < 4; oo++) {
            int o = ot*64 + o0 + oo;
            float bias = first ? (Wrb[o] + Urb[o]) : Wb[o];
            outp[(size_t)(rt*64 + r0 + rr)*256 + o] = acc[rr][oo] + bias;
        }
}

// ---------------------------------------------------------------------------
// Persistent GRU: 128 CTAs, each owns a (64-chain x 32-out) tile. Weights are
// loaded into smem once; all 64 steps run inside the kernel with a grid-wide
// release/acquire barrier between steps.
// ---------------------------------------------------------------------------
#define STEP_CTAS 128
#define WPITCH 34
#define CPITCH 68
#define GRU_SMEM_FLOATS (2*256*WPITCH + 64*CPITCH)

__device__ __forceinline__ void grid_barrier(unsigned expect)
{
    __syncthreads();
    if (threadIdx.x == 0) {
        __threadfence();
        unsigned old = atomicAdd(&g_bar_count, 1);
        if (old == STEP_CTAS - 1) {
            g_bar_count = 0;
            asm volatile("st.release.gpu.u32 [%0], %1;"
                         :: "l"(&g_bar_gen), "r"(expect) : "memory");
        } else {
            unsigned v;
            do {
                asm volatile("ld.acquire.gpu.u32 %0, [%1];"
                             : "=r"(v) : "l"(&g_bar_gen) : "memory");
            } while (v < expect);
        }
    }
    __syncthreads();
}

__global__ void __launch_bounds__(256, 1)
gru_persistent(float* __restrict__ Ca, float* __restrict__ Cb,
               const float* __restrict__ Ur, const float* __restrict__ U,
               const float* __restrict__ Ub,
               const float* __restrict__ attn)
{
    extern __shared__ float smem[];
    float* sUr = smem;                     // 256 x 34 (k x o)
    float* sU  = sUr + 256*WPITCH;
    float* sC  = sU  + 256*WPITCH;         // 64 x 68  (k x chain), single buffer

    const int bx  = blockIdx.x;
    const int ct  = bx >> 3;               // chain tile (16), 64 chains each
    const int ot  = bx & 7;                // out tile (8), 32 outs each
    const int tid = threadIdx.x;
    const int c0  = (tid & 15) * 4;
    const int o0  = (tid >> 4) * 2;

    // Load weight slices once (coalesced over k)
    #pragma unroll
    for (int e = 0; e < 32; e++) {
        int idx = e*256 + tid;             // 8192 elems
        int o = idx >> 8, k = idx & 255;
        sUr[k*WPITCH + o] = Ur[(size_t)(ot*32 + o)*256 + k];
        sU [k*WPITCH + o] = U [(size_t)(ot*32 + o)*256 + k];
    }
    const float ub0 = Ub[ot*32 + o0];
    const float ub1 = Ub[ot*32 + o0 + 1];
    __syncthreads();

    for (int t = 0; t < 64; t++) {
        const float* Cin  = (t & 1) ? Cb : Ca;
        float*       Cout = (t & 1) ? Ca : Cb;

        float aU[4][2], aV[4][2];
        #pragma unroll
        for (int a = 0; a < 4; a++) { aU[a][0]=aU[a][1]=aV[a][0]=aV[a][1]=0.0f; }

        // prefetch chunk 0
        float pf[16];
        #pragma unroll
        for (int e = 0; e < 16; e++) {
            int idx = e*256 + tid;
            int c = idx >> 6, k = idx & 63;
            pf[e] = Cin[(size_t)(ct*64 + c)*256 + k];
        }

        for (int ch = 0; ch < 4; ch++) {
            #pragma unroll
            for (int e = 0; e < 16; e++) {
                int idx = e*256 + tid;
                int c = idx >> 6, k = idx & 63;
                sC[k*CPITCH + c] = pf[e];
            }
            __syncthreads();
            if (ch < 3) {
                #pragma unroll
                for (int e = 0; e < 16; e++) {
                    int idx = e*256 + tid;
                    int c = idx >> 6, k = idx & 63;
                    pf[e] = Cin[(size_t)(ct*64 + c)*256 + (ch+1)*64 + k];
                }
            }
            const float* wr = sUr + (size_t)ch*64*WPITCH + o0;
            const float* wu = sU  + (size_t)ch*64*WPITCH + o0;
            #pragma unroll 4
            for (int k = 0; k < 64; k++) {
                float4 cv  = *(const float4*)&sC[k*CPITCH + c0];
                float2 urv = *(const float2*)&wr[k*WPITCH];
                float2 uv  = *(const float2*)&wu[k*WPITCH];
                aU[0][0]+=cv.x*urv.x; aU[0][1]+=cv.x*urv.y; aV[0][0]+=cv.x*uv.x; aV[0][1]+=cv.x*uv.y;
                aU[1][0]+=cv.y*urv.x; aU[1][1]+=cv.y*urv.y; aV[1][0]+=cv.y*uv.x; aV[1][1]+=cv.y*uv.y;
                aU[2][0]+=cv.z*urv.x; aU[2][1]+=cv.z*urv.y; aV[2][0]+=cv.z*uv.x; aV[2][1]+=cv.z*uv.y;
                aU[3][0]+=cv.w*urv.x; aU[3][1]+=cv.w*urv.y; aV[3][0]+=cv.w*uv.x; aV[3][1]+=cv.w*uv.y;
            }
            __syncthreads();
        }

        // Epilogue
        const size_t trow = (size_t)(ct*64 + t) * 256;   // n == ct for this tile
        const int o_0 = ot*32 + o0;
        const float a1_0 = g_A1[trow + o_0];
        const float a1_1 = g_A1[trow + o_0 + 1];
        const float a2_0 = g_A2[trow + o_0];
        const float a2_1 = g_A2[trow + o_0 + 1];

        #pragma unroll
        for (int cc = 0; cc < 4; cc++) {
            int b = ct*64 + c0 + cc;
            float g = attn[b*64 + t];
            float ci0 = Cin[(size_t)b*256 + o_0];
            float ci1 = Cin[(size_t)b*256 + o_0 + 1];

            float u0 = aU[cc][0] + a1_0;
            float v0 = aV[cc][0] + ub0;
            float r0 = 1.0f / (1.0f + expf(-u0));
            float h0 = tanhf(a2_0 + r0 * v0);
            Cout[(size_t)b*256 + o_0] = g*h0 + (1.0f - g)*ci0;

            float u1 = aU[cc][1] + a1_1;
            float v1 = aV[cc][1] + ub1;
            float r1 = 1.0f / (1.0f + expf(-u1));
            float h1 = tanhf(a2_1 + r1 * v1);
            Cout[(size_t)b*256 + o_0 + 1] = g*h1 + (1.0f - g)*ci1;
        }

        if (t < 63) grid_barrier((unsigned)(t + 1));
    }
}

// ---------------------------------------------------------------------------
// next_mem = relu([prevM, C, questions] @ nm_w^T + nm_b).
// ---------------------------------------------------------------------------
__global__ void final_kernel(const float* __restrict__ prevM,
                             const float* __restrict__ questions,
                             const float* __restrict__ C,
                             const float* __restrict__ nmw,
                             const float* __restrict__ nmb,
                             float* __restrict__ out)
{
    __shared__ float sX[64*36];   // k x row (32 rows)
    __shared__ float sW[64*68];   // k x out (64 outs)
    const int rt = blockIdx.x;    // 32 tiles of 32 rows
    const int ot = blockIdx.y;    // 4 tiles of 64 outs
    const int tid = threadIdx.x;
    const int tr = tid & 7, to = tid >> 3;
    const int r0 = tr*4, o0 = to*2;

    float acc[4][2];
    #pragma unroll
    for (int a = 0; a < 4; a++) { acc[a][0]=acc[a][1]=0.0f; }

    for (int k0 = 0; k0 < 768; k0 += 64) {
        __syncthreads();
        #pragma unroll
        for (int e = 0; e < 8; e++) {
            int idx = e*256 + tid;
            int r = idx >> 6, k = idx & 63;
            int kg = k0 + k;
            const float* src; int off;
            if (kg < 256)      { src = prevM;     off = kg; }
            else if (kg < 512) { src = C;         off = kg - 256; }
            else               { src = questions; off = kg - 512; }
            sX[k*36 + r] = src[(size_t)(rt*32 + r)*256 + off];
        }
        #pragma unroll
        for (int e = 0; e < 16; e++) {
            int idx = e*256 + tid;
            int o = idx >> 6, k = idx & 63;
            sW[k*68 + o] = nmw[(size_t)(ot*64 + o)*768 + k0 + k];
        }
        __syncthreads();
        #pragma unroll 4
        for (int k = 0; k < 64; k++) {
            float4 xv = *(const float4*)&sX[k*36 + r0];
            float2 wv = *(const float2*)&sW[k*68 + o0];
            acc[0][0]+=xv.x*wv.x; acc[0][1]+=xv.x*wv.y;
            acc[1][0]+=xv.y*wv.x; acc[1][1]+=xv.y*wv.y;
            acc[2][0]+=xv.z*wv.x; acc[2][1]+=xv.z*wv.y;
            acc[3][0]+=xv.w*wv.x; acc[3][1]+=xv.w*wv.y;
        }
    }
    #pragma unroll
    for (int rr = 0; rr < 4; rr++)
        #pragma unroll
        for (int oo = 0; oo < 2; oo++) {
            int o = ot*64 + o0 + oo;
            float v = acc[rr][oo] + nmb[o];
            out[(size_t)(rt*32 + r0 + rr)*256 + o] = fmaxf(v, 0.0f);
        }
}

// ---------------------------------------------------------------------------
extern "C" void kernel_launch(void* const* d_in, const int* in_sizes, int n_in,
                              void* d_out, int out_size)
{
    const float* facts     = (const float*)d_in[0];
    const float* prevM     = (const float*)d_in[1];
    const float* questions = (const float*)d_in[2];
    const int*   doc_len   = (const int*)  d_in[3];
    const float* z1w = (const float*)d_in[4];
    const float* z1b = (const float*)d_in[5];
    const float* z2w = (const float*)d_in[6];
    const float* z2b = (const float*)d_in[7];
    const float* Wrw = (const float*)d_in[8];
    const float* Wrb = (const float*)d_in[9];
    const float* Urw = (const float*)d_in[10];
    const float* Urb = (const float*)d_in[11];
    const float* Ww  = (const float*)d_in[12];
    const float* Wb  = (const float*)d_in[13];
    const float* Uw  = (const float*)d_in[14];
    const float* Ub  = (const float*)d_in[15];
    const float* nmw = (const float*)d_in[16];
    const float* nmb = (const float*)d_in[17];

    float* out      = (float*)d_out;              // next_mem first
    float* out_attn = out + NM_ELEMS;             // attn second

    const int gate_smem = GATE_SMEM_FLOATS * 4;
    cudaFuncSetAttribute(gate_kernel,
                         cudaFuncAttributeMaxDynamicSharedMemorySize, gate_smem);
    const int gru_smem = GRU_SMEM_FLOATS * 4;
    cudaFuncSetAttribute(gru_persistent,
                         cudaFuncAttributeMaxDynamicSharedMemorySize, gru_smem);

    float *Ca, *Cb;
    cudaGetSymbolAddress((void**)&Ca, g_Ca);
    cudaGetSymbolAddress((void**)&Cb, g_Cb);

    zero_kernel<<<512, 512>>>();
    gate_kernel<<<1024, 256, gate_smem>>>(facts, prevM, questions, z1w, z1b, z2w, z2b);
    softmax_kernel<<<256, 128>>>(doc_len, out_attn);
    a12_kernel<<<dim3(16, 8), 256>>>(facts, Wrw, Wrb, Urb, Ww, Wb);

    gru_persistent<<<STEP_CTAS, 256, gru_smem>>>(Ca, Cb, Urw, Uw, Ub, out_attn);

    // After t=63 (odd), final C lives in Ca
    final_kernel<<<dim3(32, 4), 256>>>(prevM, questions, Ca, nmw, nmb, out);
}

// round 3
// speedup vs baseline: 2.1808x; 1.1171x over previous
#include <cuda_runtime.h>
#include <math.h>
#include <math_constants.h>
#include <stdint.h>

// Problem dims
#define Nn 16
#define Ss 64
#define Hh 256
#define FAa 256
#define Bb (Nn*Ss)              // 1024 chains / rows
#define NM_ELEMS (Nn*Ss*Hh)     // 262144
#define ATTN_ELEMS (Nn*Ss*Ss)   // 65536

// Scratch (device globals: no allocation allowed)
__device__ float g_G [Bb*Ss];   // gate logits (n,i,j)
__device__ float g_A1[Bb*Hh];   // facts@Wr^T + Wr_b + Ur_b   (row = n*64 + t)
__device__ float g_A2[Bb*Hh];   // facts@W^T  + W_b
__device__ float g_Ca[Bb*Hh];
__device__ float g_Cb[Bb*Hh];

// Grid barrier state for the persistent GRU kernel
__device__ unsigned g_bar_count;
__device__ unsigned g_bar_gen;

// ---------------------------------------------------------------------------
// Helpers
// ---------------------------------------------------------------------------
__device__ __forceinline__ void split_tf32(float x, uint32_t& hi, uint32_t& lo)
{
    asm("cvt.rna.tf32.f32 %0, %1;" : "=r"(hi) : "f"(x));
    float r = x - __uint_as_float(hi);
    asm("cvt.rna.tf32.f32 %0, %1;" : "=r"(lo) : "f"(r));
}

__device__ __forceinline__ void mma_tf32(float* d,
                                         uint32_t a0, uint32_t a1, uint32_t a2, uint32_t a3,
                                         uint32_t b0, uint32_t b1)
{
    asm volatile(
        "mma.sync.aligned.m16n8k8.row.col.f32.tf32.tf32.f32 "
        "{%0,%1,%2,%3}, {%4,%5,%6,%7}, {%8,%9}, {%0,%1,%2,%3};"
        : "+f"(d[0]), "+f"(d[1]), "+f"(d[2]), "+f"(d[3])
        : "r"(a0), "r"(a1), "r"(a2), "r"(a3), "r"(b0), "r"(b1));
}

__device__ __forceinline__ float fast_tanh(float x)
{
    float e = __expf(2.0f * x);
    return 1.0f - __fdividef(2.0f, e + 1.0f);
}
__device__ __forceinline__ float fast_sigmoid(float x)
{
    float e = __expf(-x);
    return __fdividef(1.0f, 1.0f + e);
}

// ---------------------------------------------------------------------------
// Zero initial GRU state + reset barrier
// ---------------------------------------------------------------------------
__global__ void zero_kernel() {
    int i = blockIdx.x * 512 + threadIdx.x;
    g_Ca[i] = 0.0f;
    if (i == 0) { g_bar_count = 0; g_bar_gen = 0; }
}

// ---------------------------------------------------------------------------
// Gate MLP with 3xTF32 tensor-core GEMM.
// Per CTA = one (n,i). T[64 j x 256 a] = Z[64 x 1024] @ z1w^T, then
// G[j] = sum_a tanh(T+b1)*z2w + z2b.
// Z built on the fly into register fragments from smem-staged facts.
// z1w streamed in 32-wide K chunks (kg = 32*c contiguous) through a
// permuted smem tile (pairs (k, k+4) adjacent for float2 frag loads).
// ---------------------------------------------------------------------------
#define SFP 260                        // facts pitch (16B-aligned rows, conflict-free frag reads)
#define SBP 34                         // z1w chunk pitch
#define GATE_SMEM_FLOATS (64*SFP + 4*256 + 1024 + 256*SBP)

__global__ void __launch_bounds__(256, 1)
gate_kernel(const float* __restrict__ facts,
            const float* __restrict__ prevM,
            const float* __restrict__ questions,
            const float* __restrict__ z1w,
            const float* __restrict__ z1b,
            const float* __restrict__ z2w,
            const float* __restrict__ z2b)
{
    extern __shared__ float smem[];
    float* sf  = smem;                 // 64 x 260 facts rows for this n
    float* sq  = sf  + 64*SFP;         // 256
    float* sm_ = sq  + 256;            // 256
    float* sb1 = sm_ + 256;            // 256
    float* sz2 = sb1 + 256;            // 256
    float* red = sz2 + 256;            // 64 x 16 reduction buffer
    float* sB  = red + 1024;           // 256 x 34 z1w chunk (k-permuted)

    const int tid = threadIdx.x;
    const int ni  = blockIdx.x;        // n*64 + i
    const int n   = ni >> 6;

    const float* frow = facts + (size_t)n * Ss * Hh;

    // Stage facts (float4), q, m, b1, z2
    {
        const float4* src = (const float4*)frow;
        #pragma unroll
        for (int e = 0; e < 16; e++) {
            int idx = e*256 + tid;             // 4096 float4
            int j = idx >> 6, h4 = idx & 63;
            *(float4*)&sf[j*SFP + h4*4] = src[idx];
        }
        sq [tid] = questions[(size_t)ni * Hh + tid];
        sm_[tid] = prevM[(size_t)ni * Hh + tid];
        sb1[tid] = z1b[tid];
        sz2[tid] = z2w[tid];
    }

    const int lane = tid & 31, wid = tid >> 5;
    const int g   = lane >> 2;         // 0..7
    const int tig = lane & 3;          // 0..3
    const int wm  = wid & 1;           // m half: rows [32*wm, 32*wm+32)
    const int wn  = wid >> 1;          // n quarter: a in [64*wn, 64*wn+64)

    float acc[2][8][4];
    #pragma unroll
    for (int mt = 0; mt < 2; mt++)
        #pragma unroll
        for (int nt = 0; nt < 8; nt++)
            #pragma unroll
            for (int v = 0; v < 4; v++) acc[mt][nt][v] = 0.0f;

    // z1w row for this thread (loader: thread tid owns row a=tid)
    const float* z1wp = z1w + (size_t)tid * 1024;

    // Prefetch chunk 0 and store
    float4 pf[8];
    #pragma unroll
    for (int u = 0; u < 8; u++) pf[u] = *(const float4*)(z1wp + u*4);
    #pragma unroll
    for (int u = 0; u < 4; u++) {
        float4 A4 = pf[2*u], B4 = pf[2*u+1];
        float2* dst = (float2*)&sB[tid*SBP + 8*u];
        dst[0] = make_float2(A4.x, B4.x);
        dst[1] = make_float2(A4.y, B4.y);
        dst[2] = make_float2(A4.z, B4.z);
        dst[3] = make_float2(A4.w, B4.w);
    }
    __syncthreads();

    for (int c = 0; c < 32; c++) {
        // Prefetch next chunk into registers (overlaps with mma below)
        if (c < 31) {
            const float* p = z1wp + (c+1)*32;
            #pragma unroll
            for (int u = 0; u < 8; u++) pf[u] = *(const float4*)(p + u*4);
        }

        const int  b     = c >> 3;
        const int  h0    = (c & 7) * 32;
        const float* tvec = (b & 1) ? sm_ : sq;
        const bool isabs = (b >= 2);

        #pragma unroll
        for (int ks = 0; ks < 4; ks++) {
            const int kc = h0 + ks*8;
            float t0 = tvec[kc + tig];
            float t1 = tvec[kc + tig + 4];

            uint32_t ahi[2][4], alo[2][4];
            #pragma unroll
            for (int mt = 0; mt < 2; mt++) {
                const float* fb = sf + (32*wm + 16*mt + g)*SFP + kc;
                float f00 = fb[tig];
                float f01 = fb[tig + 4];
                float f10 = fb[8*SFP + tig];
                float f11 = fb[8*SFP + tig + 4];
                float z00 = isabs ? fabsf(f00 - t0) : f00 * t0;
                float z10 = isabs ? fabsf(f10 - t0) : f10 * t0;
                float z01 = isabs ? fabsf(f01 - t1) : f01 * t1;
                float z11 = isabs ? fabsf(f11 - t1) : f11 * t1;
                split_tf32(z00, ahi[mt][0], alo[mt][0]);
                split_tf32(z10, ahi[mt][1], alo[mt][1]);
                split_tf32(z01, ahi[mt][2], alo[mt][2]);
                split_tf32(z11, ahi[mt][3], alo[mt][3]);
            }

            #pragma unroll
            for (int nt = 0; nt < 8; nt++) {
                float2 wv = *(const float2*)&sB[(64*wn + 8*nt + g)*SBP + ks*8 + 2*tig];
                uint32_t bh0, bl0, bh1, bl1;
                split_tf32(wv.x, bh0, bl0);
                split_tf32(wv.y, bh1, bl1);
                #pragma unroll
                for (int mt = 0; mt < 2; mt++) {
                    float* d = acc[mt][nt];
                    mma_tf32(d, ahi[mt][0], ahi[mt][1], ahi[mt][2], ahi[mt][3], bh0, bh1);
                    mma_tf32(d, alo[mt][0], alo[mt][1], alo[mt][2], alo[mt][3], bh0, bh1);
                    mma_tf32(d, ahi[mt][0], ahi[mt][1], ahi[mt][2], ahi[mt][3], bl0, bl1);
                }
            }
        }

        __syncthreads();
        if (c < 31) {
            #pragma unroll
            for (int u = 0; u < 4; u++) {
                float4 A4 = pf[2*u], B4 = pf[2*u+1];
                float2* dst = (float2*)&sB[tid*SBP + 8*u];
                dst[0] = make_float2(A4.x, B4.x);
                dst[1] = make_float2(A4.y, B4.y);
                dst[2] = make_float2(A4.z, B4.z);
                dst[3] = make_float2(A4.w, B4.w);
            }
            __syncthreads();
        }
    }

    // Epilogue: tanh + z2 dot, per-thread partials then smem reduce.
    #pragma unroll
    for (int mt = 0; mt < 2; mt++) {
        #pragma unroll
        for (int half = 0; half < 2; half++) {
            int j = 32*wm + 16*mt + 8*half + g;
            float s = 0.0f;
            #pragma unroll
            for (int nt = 0; nt < 8; nt++) {
                #pragma unroll
                for (int w2 = 0; w2 < 2; w2++) {
                    int a = 64*wn + 8*nt + 2*tig + w2;
                    float x = acc[mt][nt][half*2 + w2] + sb1[a];
                    s += fast_tanh(x) * sz2[a];
                }
            }
            red[j*16 + wn*4 + tig] = s;
        }
    }
    __syncthreads();
    if (tid < 64) {
        float s = z2b[0];
        #pragma unroll
        for (int t2 = 0; t2 < 16; t2++) s += red[tid*16 + t2];
        g_G[ni*64 + tid] = s;
    }
}

// ---------------------------------------------------------------------------
// Masked softmax over facts axis j. One warp per (n,i) row.
// ---------------------------------------------------------------------------
__global__ void softmax_kernel(const int* __restrict__ doc_len,
                               float* __restrict__ out_attn)
{
    int row  = blockIdx.x * 4 + (threadIdx.x >> 5);
    int lane = threadIdx.x & 31;
    int n  = row >> 6;
    int dl = doc_len[n];

    float v0 = g_G[row*64 + lane];
    float v1 = g_G[row*64 + 32 + lane];
    float x0 = (lane      < dl && v0 != 0.0f) ? v0 : -CUDART_INF_F;
    float x1 = (lane + 32 < dl && v1 != 0.0f) ? v1 : -CUDART_INF_F;

    float mx = fmaxf(x0, x1);
    #pragma unroll
    for (int o = 16; o >= 1; o >>= 1)
        mx = fmaxf(mx, __shfl_xor_sync(0xffffffffu, mx, o));

    float e0 = expf(x0 - mx);
    float e1 = expf(x1 - mx);
    float s = e0 + e1;
    #pragma unroll
    for (int o = 16; o >= 1; o >>= 1)
        s += __shfl_xor_sync(0xffffffffu, s, o);

    float inv = 1.0f / s;
    out_attn[row*64 + lane]      = e0 * inv;
    out_attn[row*64 + 32 + lane] = e1 * inv;
}

// ---------------------------------------------------------------------------
// A1 = facts@Wr^T + Wr_b + Ur_b ; A2 = facts@W^T + W_b
// ---------------------------------------------------------------------------
__global__ void a12_kernel(const float* __restrict__ facts,
                           const float* __restrict__ Wr, const float* __restrict__ Wrb,
                           const float* __restrict__ Urb,
                           const float* __restrict__ W,  const float* __restrict__ Wb)
{
    __shared__ float sX[64*68];
    __shared__ float sWm[64*68];
    const int rt = blockIdx.x;
    const int yy = blockIdx.y;
    const bool first = (yy < 4);
    const int ot = first ? yy : yy - 4;
    const float* Wm = first ? Wr : W;
    float* outp = first ? g_A1 : g_A2;

    const int tid = threadIdx.x;
    const int tr = tid & 15, to = tid >> 4;
    const int r0 = tr*4, o0 = to*4;
    float acc[4][4];
    #pragma unroll
    for (int a = 0; a < 4; a++)
        #pragma unroll
        for (int b = 0; b < 4; b++) acc[a][b] = 0.0f;

    for (int k0 = 0; k0 < 256; k0 += 64) {
        __syncthreads();
        #pragma unroll
        for (int e = 0; e < 16; e++) {
            int idx = e*256 + tid;
            int r = idx >> 6, k = idx & 63;
            sX[k*68 + r]  = facts[(size_t)(rt*64 + r)*256 + k0 + k];
            int o = r;
            sWm[k*68 + o] = Wm[(size_t)(ot*64 + o)*256 + k0 + k];
        }
        __syncthreads();
        #pragma unroll 4
        for (int k = 0; k < 64; k++) {
            float4 xv = *(const float4*)&sX[k*68 + r0];
            float4 wv = *(const float4*)&sWm[k*68 + o0];
            acc[0][0]+=xv.x*wv.x; acc[0][1]+=xv.x*wv.y; acc[0][2]+=xv.x*wv.z; acc[0][3]+=xv.x*wv.w;
            acc[1][0]+=xv.y*wv.x; acc[1][1]+=xv.y*wv.y; acc[1][2]+=xv.y*wv.z; acc[1][3]+=xv.y*wv.w;
            acc[2][0]+=xv.z*wv.x; acc[2][1]+=xv.z*wv.y; acc[2][2]+=xv.z*wv.z; acc[2][3]+=xv.z*wv.w;
            acc[3][0]+=xv.w*wv.x; acc[3][1]+=xv.w*wv.y; acc[3][2]+=xv.w*wv.z; acc[3][3]+=xv.w*wv.w;
        }
    }
    #pragma unroll
    for (int rr = 0; rr < 4; rr++)
        #pragma unroll
        for (int oo = 0; oo < 4; oo++) {
            int o = ot*64 + o0 + oo;
            float bias = first ? (Wrb[o] + Urb[o]) : Wb[o];
            outp[(size_t)(rt*64 + r0 + rr)*256 + o] = acc[rr][oo] + bias;
        }
}

// ---------------------------------------------------------------------------
// Persistent GRU: 128 CTAs, each owns a (64-chain x 32-out) tile.
// ---------------------------------------------------------------------------
#define STEP_CTAS 128
#define WPITCH 34
#define CPITCH 68
#define GRU_SMEM_FLOATS (2*256*WPITCH + 64*CPITCH)

__device__ __forceinline__ void grid_barrier(unsigned expect)
{
    __syncthreads();
    if (threadIdx.x == 0) {
        __threadfence();
        unsigned old = atomicAdd(&g_bar_count, 1);
        if (old == STEP_CTAS - 1) {
            g_bar_count = 0;
            asm volatile("st.release.gpu.u32 [%0], %1;"
                         :: "l"(&g_bar_gen), "r"(expect) : "memory");
        } else {
            unsigned v;
            do {
                asm volatile("ld.acquire.gpu.u32 %0, [%1];"
                             : "=r"(v) : "l"(&g_bar_gen) : "memory");
            } while (v < expect);
        }
    }
    __syncthreads();
}

__global__ void __launch_bounds__(256, 1)
gru_persistent(float* __restrict__ Ca, float* __restrict__ Cb,
               const float* __restrict__ Ur, const float* __restrict__ U,
               const float* __restrict__ Ub,
               const float* __restrict__ attn)
{
    extern __shared__ float smem[];
    float* sUr = smem;                     // 256 x 34 (k x o)
    float* sU  = sUr + 256*WPITCH;
    float* sC  = sU  + 256*WPITCH;         // 64 x 68  (k x chain)

    const int bx  = blockIdx.x;
    const int ct  = bx >> 3;               // chain tile (16), 64 chains each
    const int ot  = bx & 7;                // out tile (8), 32 outs each
    const int tid = threadIdx.x;
    const int c0  = (tid & 15) * 4;
    const int o0  = (tid >> 4) * 2;

    #pragma unroll
    for (int e = 0; e < 32; e++) {
        int idx = e*256 + tid;             // 8192 elems
        int o = idx >> 8, k = idx & 255;
        sUr[k*WPITCH + o] = Ur[(size_t)(ot*32 + o)*256 + k];
        sU [k*WPITCH + o] = U [(size_t)(ot*32 + o)*256 + k];
    }
    const float ub0 = Ub[ot*32 + o0];
    const float ub1 = Ub[ot*32 + o0 + 1];
    __syncthreads();

    for (int t = 0; t < 64; t++) {
        const float* Cin  = (t & 1) ? Cb : Ca;
        float*       Cout = (t & 1) ? Ca : Cb;

        float aU[4][2], aV[4][2];
        #pragma unroll
        for (int a = 0; a < 4; a++) { aU[a][0]=aU[a][1]=aV[a][0]=aV[a][1]=0.0f; }

        float pf[16];
        #pragma unroll
        for (int e = 0; e < 16; e++) {
            int idx = e*256 + tid;
            int c = idx >> 6, k = idx & 63;
            pf[e] = Cin[(size_t)(ct*64 + c)*256 + k];
        }

        for (int ch = 0; ch < 4; ch++) {
            #pragma unroll
            for (int e = 0; e < 16; e++) {
                int idx = e*256 + tid;
                int c = idx >> 6, k = idx & 63;
                sC[k*CPITCH + c] = pf[e];
            }
            __syncthreads();
            if (ch < 3) {
                #pragma unroll
                for (int e = 0; e < 16; e++) {
                    int idx = e*256 + tid;
                    int c = idx >> 6, k = idx & 63;
                    pf[e] = Cin[(size_t)(ct*64 + c)*256 + (ch+1)*64 + k];
                }
            }
            const float* wr = sUr + (size_t)ch*64*WPITCH + o0;
            const float* wu = sU  + (size_t)ch*64*WPITCH + o0;
            #pragma unroll 4
            for (int k = 0; k < 64; k++) {
                float4 cv  = *(const float4*)&sC[k*CPITCH + c0];
                float2 urv = *(const float2*)&wr[k*WPITCH];
                float2 uv  = *(const float2*)&wu[k*WPITCH];
                aU[0][0]+=cv.x*urv.x; aU[0][1]+=cv.x*urv.y; aV[0][0]+=cv.x*uv.x; aV[0][1]+=cv.x*uv.y;
                aU[1][0]+=cv.y*urv.x; aU[1][1]+=cv.y*urv.y; aV[1][0]+=cv.y*uv.x; aV[1][1]+=cv.y*uv.y;
                aU[2][0]+=cv.z*urv.x; aU[2][1]+=cv.z*urv.y; aV[2][0]+=cv.z*uv.x; aV[2][1]+=cv.z*uv.y;
                aU[3][0]+=cv.w*urv.x; aU[3][1]+=cv.w*urv.y; aV[3][0]+=cv.w*uv.x; aV[3][1]+=cv.w*uv.y;
            }
            __syncthreads();
        }

        const size_t trow = (size_t)(ct*64 + t) * 256;
        const int o_0 = ot*32 + o0;
        const float a1_0 = g_A1[trow + o_0];
        const float a1_1 = g_A1[trow + o_0 + 1];
        const float a2_0 = g_A2[trow + o_0];
        const float a2_1 = g_A2[trow + o_0 + 1];

        #pragma unroll
        for (int cc = 0; cc < 4; cc++) {
            int b = ct*64 + c0 + cc;
            float g = attn[b*64 + t];
            float ci0 = Cin[(size_t)b*256 + o_0];
            float ci1 = Cin[(size_t)b*256 + o_0 + 1];

            float u0 = aU[cc][0] + a1_0;
            float v0 = aV[cc][0] + ub0;
            float r0 = fast_sigmoid(u0);
            float h0 = fast_tanh(a2_0 + r0 * v0);
            Cout[(size_t)b*256 + o_0] = g*h0 + (1.0f - g)*ci0;

            float u1 = aU[cc][1] + a1_1;
            float v1 = aV[cc][1] + ub1;
            float r1 = fast_sigmoid(u1);
            float h1 = fast_tanh(a2_1 + r1 * v1);
            Cout[(size_t)b*256 + o_0 + 1] = g*h1 + (1.0f - g)*ci1;
        }

        if (t < 63) grid_barrier((unsigned)(t + 1));
    }
}

// ---------------------------------------------------------------------------
// next_mem = relu([prevM, C, questions] @ nm_w^T + nm_b).
// ---------------------------------------------------------------------------
__global__ void final_kernel(const float* __restrict__ prevM,
                             const float* __restrict__ questions,
                             const float* __restrict__ C,
                             const float* __restrict__ nmw,
                             const float* __restrict__ nmb,
                             float* __restrict__ out)
{
    __shared__ float sX[64*36];   // k x row (32 rows)
    __shared__ float sW[64*68];   // k x out (64 outs)
    const int rt = blockIdx.x;    // 32 tiles of 32 rows
    const int ot = blockIdx.y;    // 4 tiles of 64 outs
    const int tid = threadIdx.x;
    const int tr = tid & 7, to = tid >> 3;
    const int r0 = tr*4, o0 = to*2;

    float acc[4][2];
    #pragma unroll
    for (int a = 0; a < 4; a++) { acc[a][0]=acc[a][1]=0.0f; }

    for (int k0 = 0; k0 < 768; k0 += 64) {
        __syncthreads();
        #pragma unroll
        for (int e = 0; e < 8; e++) {
            int idx = e*256 + tid;
            int r = idx >> 6, k = idx & 63;
            int kg = k0 + k;
            const float* src; int off;
            if (kg < 256)      { src = prevM;     off = kg; }
            else if (kg < 512) { src = C;         off = kg - 256; }
            else               { src = questions; off = kg - 512; }
            sX[k*36 + r] = src[(size_t)(rt*32 + r)*256 + off];
        }
        #pragma unroll
        for (int e = 0; e < 16; e++) {
            int idx = e*256 + tid;
            int o = idx >> 6, k = idx & 63;
            sW[k*68 + o] = nmw[(size_t)(ot*64 + o)*768 + k0 + k];
        }
        __syncthreads();
        #pragma unroll 4
        for (int k = 0; k < 64; k++) {
            float4 xv = *(const float4*)&sX[k*36 + r0];
            float2 wv = *(const float2*)&sW[k*68 + o0];
            acc[0][0]+=xv.x*wv.x; acc[0][1]+=xv.x*wv.y;
            acc[1][0]+=xv.y*wv.x; acc[1][1]+=xv.y*wv.y;
            acc[2][0]+=xv.z*wv.x; acc[2][1]+=xv.z*wv.y;
            acc[3][0]+=xv.w*wv.x; acc[3][1]+=xv.w*wv.y;
        }
    }
    #pragma unroll
    for (int rr = 0; rr < 4; rr++)
        #pragma unroll
        for (int oo = 0; oo < 2; oo++) {
            int o = ot*64 + o0 + oo;
            float v = acc[rr][oo] + nmb[o];
            out[(size_t)(rt*32 + r0 + rr)*256 + o] = fmaxf(v, 0.0f);
        }
}

// ---------------------------------------------------------------------------
extern "C" void kernel_launch(void* const* d_in, const int* in_sizes, int n_in,
                              void* d_out, int out_size)
{
    const float* facts     = (const float*)d_in[0];
    const float* prevM     = (const float*)d_in[1];
    const float* questions = (const float*)d_in[2];
    const int*   doc_len   = (const int*)  d_in[3];
    const float* z1w = (const float*)d_in[4];
    const float* z1b = (const float*)d_in[5];
    const float* z2w = (const float*)d_in[6];
    const float* z2b = (const float*)d_in[7];
    const float* Wrw = (const float*)d_in[8];
    const float* Wrb = (const float*)d_in[9];
    const float* Urw = (const float*)d_in[10];
    const float* Urb = (const float*)d_in[11];
    const float* Ww  = (const float*)d_in[12];
    const float* Wb  = (const float*)d_in[13];
    const float* Uw  = (const float*)d_in[14];
    const float* Ub  = (const float*)d_in[15];
    const float* nmw = (const float*)d_in[16];
    const float* nmb = (const float*)d_in[17];

    float* out      = (float*)d_out;              // next_mem first
    float* out_attn = out + NM_ELEMS;             // attn second

    const int gate_smem = GATE_SMEM_FLOATS * 4;
    cudaFuncSetAttribute(gate_kernel,
                         cudaFuncAttributeMaxDynamicSharedMemorySize, gate_smem);
    const int gru_smem = GRU_SMEM_FLOATS * 4;
    cudaFuncSetAttribute(gru_persistent,
                         cudaFuncAttributeMaxDynamicSharedMemorySize, gru_smem);

    float *Ca, *Cb;
    cudaGetSymbolAddress((void**)&Ca, g_Ca);
    cudaGetSymbolAddress((void**)&Cb, g_Cb);

    zero_kernel<<<512, 512>>>();
    gate_kernel<<<1024, 256, gate_smem>>>(facts, prevM, questions, z1w, z1b, z2w, z2b);
    softmax_kernel<<<256, 128>>>(doc_len, out_attn);
    a12_kernel<<<dim3(16, 8), 256>>>(facts, Wrw, Wrb, Urb, Ww, Wb);

    gru_persistent<<<STEP_CTAS, 256, gru_smem>>>(Ca, Cb, Urw, Uw, Ub, out_attn);

    // After t=63 (odd), final C lives in Ca
    final_kernel<<<dim3(32, 4), 256>>>(prevM, questions, Ca, nmw, nmb, out);
}

// round 5
// speedup vs baseline: 2.8281x; 1.2968x over previous
#include <cuda_runtime.h>
#include <cuda_bf16.h>
#include <math.h>
#include <math_constants.h>
#include <stdint.h>

// Problem dims
#define Nn 16
#define Ss 64
#define Hh 256
#define FAa 256
#define Bb (Nn*Ss)              // 1024 chains / rows
#define NM_ELEMS (Nn*Ss*Hh)     // 262144
#define ATTN_ELEMS (Nn*Ss*Ss)   // 65536

// Scratch (device globals: no allocation allowed)
__device__ float g_G [Bb*Ss];   // gate logits (n,i,j)
__device__ float g_A1[Bb*Hh];
__device__ float g_A2[Bb*Hh];
__device__ float g_Ca[Bb*Hh];
__device__ float g_Cb[Bb*Hh];
__device__ __nv_bfloat16 g_Whi[256*1024];   // z1w split hi
__device__ __nv_bfloat16 g_Wlo[256*1024];   // z1w split lo

__device__ unsigned g_bar_count;
__device__ unsigned g_bar_gen;

// ---------------------------------------------------------------------------
// Helpers
// ---------------------------------------------------------------------------
__device__ __forceinline__ float fast_tanh(float x)
{
    float e = __expf(2.0f * x);
    return 1.0f - __fdividef(2.0f, e + 1.0f);
}
__device__ __forceinline__ float fast_sigmoid(float x)
{
    float e = __expf(-x);
    return __fdividef(1.0f, 1.0f + e);
}

// Pack two floats to bf16x2 (x -> low, y -> high) and return residual pack too.
__device__ __forceinline__ uint32_t split2(float x, float y, uint32_t& lo)
{
    uint32_t hi;
    asm("cvt.rn.bf16x2.f32 %0, %1, %2;" : "=r"(hi) : "f"(y), "f"(x));
    float xr = x - __uint_as_float(hi << 16);
    float yr = y - __uint_as_float(hi & 0xffff0000u);
    asm("cvt.rn.bf16x2.f32 %0, %1, %2;" : "=r"(lo) : "f"(yr), "f"(xr));
    return hi;
}

__device__ __forceinline__ void mma_bf16(float* d, const uint32_t* a,
                                         uint32_t b0, uint32_t b1)
{
    asm volatile(
        "mma.sync.aligned.m16n8k16.row.col.f32.bf16.bf16.f32 "
        "{%0,%1,%2,%3}, {%4,%5,%6,%7}, {%8,%9}, {%0,%1,%2,%3};"
        : "+f"(d[0]), "+f"(d[1]), "+f"(d[2]), "+f"(d[3])
        : "r"(a[0]), "r"(a[1]), "r"(a[2]), "r"(a[3]), "r"(b0), "r"(b1));
}

__device__ __forceinline__ void ldm_x4(uint32_t* r, uint32_t addr)
{
    asm volatile("ldmatrix.sync.aligned.m8n8.x4.shared.b16 {%0,%1,%2,%3}, [%4];"
        : "=r"(r[0]), "=r"(r[1]), "=r"(r[2]), "=r"(r[3]) : "r"(addr));
}

__device__ __forceinline__ void cp16(uint32_t dst, const void* src)
{
    asm volatile("cp.async.cg.shared.global [%0], [%1], 16;" :: "r"(dst), "l"(src));
}

// ---------------------------------------------------------------------------
// Zero initial GRU state + reset barrier
// ---------------------------------------------------------------------------
__global__ void zero_kernel() {
    int i = blockIdx.x * 512 + threadIdx.x;
    g_Ca[i] = 0.0f;
    if (i == 0) { g_bar_count = 0; g_bar_gen = 0; }
}

// ---------------------------------------------------------------------------
// Pre-split z1w into bf16 hi/lo
// ---------------------------------------------------------------------------
__global__ void splitw_kernel(const float* __restrict__ z1w) {
    int i = blockIdx.x * 256 + threadIdx.x;
    #pragma unroll
    for (int e = 0; e < 4; e++) {
        int idx = e * 65536 + i;
        float w = z1w[idx];
        __nv_bfloat16 h = __float2bfloat16_rn(w);
        g_Whi[idx] = h;
        g_Wlo[idx] = __float2bfloat16_rn(w - __bfloat162float(h));
    }
}

// ---------------------------------------------------------------------------
// Gate MLP via bf16-split mma.sync.m16n8k16.
// One CTA per (n, i-pair): D[128x256] = Z[128x1024] @ z1w^T (3 split terms),
// rows 0..63 = (i0, j), rows 64..127 = (i1, j).
// W streamed in K=64 chunks (bf16 hi/lo), cp.async double-buffered;
// Z fragments built in registers from fp32 facts in smem.
// ---------------------------------------------------------------------------
#define WOFF    0
#define WBUFSZ  73728              // one buffer: 256 rows x 144B (hi) + same (lo)
#define WHALF   36864
#define SFOFF   147456             // 64 x 258 fp32 facts
#define QOFF    (SFOFF + 66048)    // q0,q1,m0,m1
#define B1OFF   (QOFF + 4096)
#define Z2OFF   (B1OFF + 1024)
#define REDOFF  (Z2OFF + 1024)     // 128 x 8 floats
#define GATE_SMEM_BYTES (REDOFF + 4096)   // 223744

__global__ void __launch_bounds__(256, 1)
gate_kernel(const float* __restrict__ facts,
            const float* __restrict__ prevM,
            const float* __restrict__ questions,
            const float* __restrict__ z1b,
            const float* __restrict__ z2w,
            const float* __restrict__ z2b)
{
    extern __shared__ char smc[];
    float* sf  = (float*)(smc + SFOFF);
    float* sQ0 = (float*)(smc + QOFF);
    float* sQ1 = sQ0 + 256;
    float* sM0 = sQ1 + 256;
    float* sM1 = sM0 + 256;
    float* sb1 = (float*)(smc + B1OFF);
    float* sz2 = (float*)(smc + Z2OFF);
    float* red = (float*)(smc + REDOFF);
    const uint32_t smbase = (uint32_t)__cvta_generic_to_shared(smc);

    const int tid  = threadIdx.x;
    const int lane = tid & 31;
    const int wid  = tid >> 5;
    const int g    = lane >> 2;
    const int tg   = lane & 3;
    const int wm   = wid & 3;          // M 32-slice
    const int wn   = wid >> 2;         // N 128-slice

    const int bx  = blockIdx.x;        // 0..511
    const int n   = bx >> 5;
    const int ip  = bx & 31;
    const int ni0 = n*64 + ip*2;

    // Stage facts (fp32, pitch 258) + q/m/b1/z2
    {
        const float2* f2 = (const float2*)(facts + (size_t)n * Ss * Hh);
        #pragma unroll
        for (int e = 0; e < 32; e++) {
            int idx = e*256 + tid;
            int j = idx >> 7, h2 = idx & 127;
            *(float2*)&sf[j*258 + h2*2] = f2[idx];
        }
        sQ0[tid] = questions[(size_t)ni0*256 + tid];
        sQ1[tid] = questions[(size_t)(ni0+1)*256 + tid];
        sM0[tid] = prevM[(size_t)ni0*256 + tid];
        sM1[tid] = prevM[(size_t)(ni0+1)*256 + tid];
        sb1[tid] = z1b[tid];
        sz2[tid] = z2w[tid];
    }

    // Prologue: W chunk 0 into buffer 0
    {
        const char* gh = (const char*)(g_Whi + (size_t)tid*1024);
        const char* gl = (const char*)(g_Wlo + (size_t)tid*1024);
        uint32_t dh = smbase + WOFF + (uint32_t)tid*144;
        uint32_t dl = dh + WHALF;
        #pragma unroll
        for (int u = 0; u < 8; u++) { cp16(dh + u*16, gh + u*16); cp16(dl + u*16, gl + u*16); }
        asm volatile("cp.async.commit_group;");
        asm volatile("cp.async.wait_group 0;");
    }
    __syncthreads();

    float acc[2][16][4];
    #pragma unroll
    for (int mt = 0; mt < 2; mt++)
        #pragma unroll
        for (int nt = 0; nt < 16; nt++)
            #pragma unroll
            for (int v = 0; v < 4; v++) acc[mt][nt][v] = 0.0f;

    // B-tile base address for this thread's ldmatrix role
    const uint32_t broff = (uint32_t)((wn*128 + ((lane>>4)&1)*8 + (lane&7)) * 144
                                      + ((lane>>3)&1)*16);

    for (int c = 0; c < 16; c++) {
        // Kick cp.async for chunk c+1
        if (c < 15) {
            const char* gh = (const char*)(g_Whi + (size_t)tid*1024 + (c+1)*64);
            const char* gl = (const char*)(g_Wlo + (size_t)tid*1024 + (c+1)*64);
            uint32_t dh = smbase + WOFF + (uint32_t)(((c+1)&1)*WBUFSZ) + (uint32_t)tid*144;
            uint32_t dl = dh + WHALF;
            #pragma unroll
            for (int u = 0; u < 8; u++) { cp16(dh + u*16, gh + u*16); cp16(dl + u*16, gl + u*16); }
            asm volatile("cp.async.commit_group;");
        }

        const int  bterm = c >> 2;
        const int  h0    = (c & 3) * 64;
        const bool isabs = (bterm >= 2);
        const uint32_t wbase = smbase + WOFF + (uint32_t)((c&1)*WBUFSZ);

        #pragma unroll
        for (int ks = 0; ks < 4; ks++) {
            const int h = h0 + ks*16;

            // Build A fragments (hi/lo) in registers
            uint32_t Ah[2][4], Al[2][4];
            #pragma unroll
            for (int mt = 0; mt < 2; mt++) {
                const int rb   = wm*32 + mt*16 + g;
                const int isel = rb >> 6;
                const float* tv = (bterm & 1) ? (isel ? sM1 : sM0)
                                              : (isel ? sQ1 : sQ0);
                const int j0 = rb & 63;
                const float* fr0 = &sf[j0*258 + h + tg*2];
                const float* fr1 = fr0 + 8*258;
                float2 t0  = *(const float2*)&tv[h + tg*2];
                float2 t1  = *(const float2*)&tv[h + tg*2 + 8];
                float2 fa  = *(const float2*)fr0;        // row g,   k tg*2
                float2 fA  = *(const float2*)(fr0 + 8);  // row g,   k tg*2+8
                float2 fb  = *(const float2*)fr1;        // row g+8, k tg*2
                float2 fB  = *(const float2*)(fr1 + 8);  // row g+8, k tg*2+8
                float z00, z01, z10, z11, z20, z21, z30, z31;
                if (isabs) {
                    z00 = fabsf(fa.x - t0.x); z01 = fabsf(fa.y - t0.y);
                    z10 = fabsf(fb.x - t0.x); z11 = fabsf(fb.y - t0.y);
                    z20 = fabsf(fA.x - t1.x); z21 = fabsf(fA.y - t1.y);
                    z30 = fabsf(fB.x - t1.x); z31 = fabsf(fB.y - t1.y);
                } else {
                    z00 = fa.x * t0.x; z01 = fa.y * t0.y;
                    z10 = fb.x * t0.x; z11 = fb.y * t0.y;
                    z20 = fA.x * t1.x; z21 = fA.y * t1.y;
                    z30 = fB.x * t1.x; z31 = fB.y * t1.y;
                }
                Ah[mt][0] = split2(z00, z01, Al[mt][0]);
                Ah[mt][1] = split2(z10, z11, Al[mt][1]);
                Ah[mt][2] = split2(z20, z21, Al[mt][2]);
                Ah[mt][3] = split2(z30, z31, Al[mt][3]);
            }

            // B fragments via ldmatrix + 3-term mma
            #pragma unroll
            for (int p = 0; p < 8; p++) {
                uint32_t ah = wbase + broff + (uint32_t)(p*16*144 + ks*32);
                uint32_t bh[4], bl[4];
                ldm_x4(bh, ah);
                ldm_x4(bl, ah + WHALF);
                #pragma unroll
                for (int q2 = 0; q2 < 2; q2++) {
                    const int nt = p*2 + q2;
                    uint32_t b0h = bh[q2*2], b1h = bh[q2*2+1];
                    uint32_t b0l = bl[q2*2], b1l = bl[q2*2+1];
                    mma_bf16(acc[0][nt], Ah[0], b0h, b1h);
                    mma_bf16(acc[1][nt], Ah[1], b0h, b1h);
                    mma_bf16(acc[0][nt], Al[0], b0h, b1h);
                    mma_bf16(acc[1][nt], Al[1], b0h, b1h);
                    mma_bf16(acc[0][nt], Ah[0], b0l, b1l);
                    mma_bf16(acc[1][nt], Ah[1], b0l, b1l);
                }
            }
        }

        if (c < 15) asm volatile("cp.async.wait_group 0;");
        __syncthreads();
    }

    // Epilogue: tanh + z2 dot, partial per (row, wn, tg), then reduce
    #pragma unroll
    for (int mt = 0; mt < 2; mt++) {
        #pragma unroll
        for (int rh = 0; rh < 2; rh++) {
            const int r = wm*32 + mt*16 + rh*8 + g;
            float s = 0.0f;
            #pragma unroll
            for (int nt = 0; nt < 16; nt++) {
                #pragma unroll
                for (int cc = 0; cc < 2; cc++) {
                    const int a = wn*128 + nt*8 + tg*2 + cc;
                    float x = acc[mt][nt][rh*2 + cc] + sb1[a];
                    s += fast_tanh(x) * sz2[a];
                }
            }
            red[r*8 + wn*4 + tg] = s;
        }
    }
    __syncthreads();
    if (tid < 128) {
        float G = z2b[0];
        #pragma unroll
        for (int u = 0; u < 8; u++) G += red[tid*8 + u];
        const int isel = tid >> 6, j = tid & 63;
        g_G[(ni0 + isel)*64 + j] = G;
    }
}

// ---------------------------------------------------------------------------
// Masked softmax over facts axis j. One warp per (n,i) row.
// ---------------------------------------------------------------------------
__global__ void softmax_kernel(const int* __restrict__ doc_len,
                               float* __restrict__ out_attn)
{
    int row  = blockIdx.x * 4 + (threadIdx.x >> 5);
    int lane = threadIdx.x & 31;
    int n  = row >> 6;
    int dl = doc_len[n];

    float v0 = g_G[row*64 + lane];
    float v1 = g_G[row*64 + 32 + lane];
    float x0 = (lane      < dl && v0 != 0.0f) ? v0 : -CUDART_INF_F;
    float x1 = (lane + 32 < dl && v1 != 0.0f) ? v1 : -CUDART_INF_F;

    float mx = fmaxf(x0, x1);
    #pragma unroll
    for (int o = 16; o >= 1; o >>= 1)
        mx = fmaxf(mx, __shfl_xor_sync(0xffffffffu, mx, o));

    float e0 = expf(x0 - mx);
    float e1 = expf(x1 - mx);
    float s = e0 + e1;
    #pragma unroll
    for (int o = 16; o >= 1; o >>= 1)
        s += __shfl_xor_sync(0xffffffffu, s, o);

    float inv = 1.0f / s;
    out_attn[row*64 + lane]      = e0 * inv;
    out_attn[row*64 + 32 + lane] = e1 * inv;
}

// ---------------------------------------------------------------------------
// A1 = facts@Wr^T + Wr_b + Ur_b ; A2 = facts@W^T + W_b
// ---------------------------------------------------------------------------
__global__ void a12_kernel(const float* __restrict__ facts,
                           const float* __restrict__ Wr, const float* __restrict__ Wrb,
                           const float* __restrict__ Urb,
                           const float* __restrict__ W,  const float* __restrict__ Wb)
{
    __shared__ float sX[64*68];
    __shared__ float sWm[64*68];
    const int rt = blockIdx.x;
    const int yy = blockIdx.y;
    const bool first = (yy < 4);
    const int ot = first ? yy : yy - 4;
    const float* Wm = first ? Wr : W;
    float* outp = first ? g_A1 : g_A2;

    const int tid = threadIdx.x;
    const int tr = tid & 15, to = tid >> 4;
    const int r0 = tr*4, o0 = to*4;
    float acc[4][4];
    #pragma unroll
    for (int a = 0; a < 4; a++)
        #pragma unroll
        for (int b = 0; b < 4; b++) acc[a][b] = 0.0f;

    for (int k0 = 0; k0 < 256; k0 += 64) {
        __syncthreads();
        #pragma unroll
        for (int e = 0; e < 16; e++) {
            int idx = e*256 + tid;
            int r = idx >> 6, k = idx & 63;
            sX[k*68 + r]  = facts[(size_t)(rt*64 + r)*256 + k0 + k];
            int o = r;
            sWm[k*68 + o] = Wm[(size_t)(ot*64 + o)*256 + k0 + k];
        }
        __syncthreads();
        #pragma unroll 4
        for (int k = 0; k < 64; k++) {
            float4 xv = *(const float4*)&sX[k*68 + r0];
            float4 wv = *(const float4*)&sWm[k*68 + o0];
            acc[0][0]+=xv.x*wv.x; acc[0][1]+=xv.x*wv.y; acc[0][2]+=xv.x*wv.z; acc[0][3]+=xv.x*wv.w;
            acc[1][0]+=xv.y*wv.x; acc[1][1]+=xv.y*wv.y; acc[1][2]+=xv.y*wv.z; acc[1][3]+=xv.y*wv.w;
            acc[2][0]+=xv.z*wv.x; acc[2][1]+=xv.z*wv.y; acc[2][2]+=xv.z*wv.z; acc[2][3]+=xv.z*wv.w;
            acc[3][0]+=xv.w*wv.x; acc[3][1]+=xv.w*wv.y; acc[3][2]+=xv.w*wv.z; acc[3][3]+=xv.w*wv.w;
        }
    }
    #pragma unroll
    for (int rr = 0; rr < 4; rr++)
        #pragma unroll
        for (int oo = 0; oo < 4; oo++) {
            int o = ot*64 + o0 + oo;
            float bias = first ? (Wrb[o] + Urb[o]) : Wb[o];
            outp[(size_t)(rt*64 + r0 + rr)*256 + o] = acc[rr][oo] + bias;
        }
}

// ---------------------------------------------------------------------------
// Persistent GRU: 128 CTAs, each owns a (64-chain x 32-out) tile.
// ---------------------------------------------------------------------------
#define STEP_CTAS 128
#define WPITCH 34
#define CPITCH 68
#define GRU_SMEM_FLOATS (2*256*WPITCH + 64*CPITCH)

__device__ __forceinline__ void grid_barrier(unsigned expect)
{
    __syncthreads();
    if (threadIdx.x == 0) {
        __threadfence();
        unsigned old = atomicAdd(&g_bar_count, 1);
        if (old == STEP_CTAS - 1) {
            g_bar_count = 0;
            asm volatile("st.release.gpu.u32 [%0], %1;"
                         :: "l"(&g_bar_gen), "r"(expect) : "memory");
        } else {
            unsigned v;
            do {
                asm volatile("ld.acquire.gpu.u32 %0, [%1];"
                             : "=r"(v) : "l"(&g_bar_gen) : "memory");
            } while (v < expect);
        }
    }
    __syncthreads();
}

__global__ void __launch_bounds__(256, 1)
gru_persistent(float* __restrict__ Ca, float* __restrict__ Cb,
               const float* __restrict__ Ur, const float* __restrict__ U,
               const float* __restrict__ Ub,
               const float* __restrict__ attn)
{
    extern __shared__ float smem[];
    float* sUr = smem;
    float* sU  = sUr + 256*WPITCH;
    float* sC  = sU  + 256*WPITCH;

    const int bx  = blockIdx.x;
    const int ct  = bx >> 3;
    const int ot  = bx & 7;
    const int tid = threadIdx.x;
    const int c0  = (tid & 15) * 4;
    const int o0  = (tid >> 4) * 2;

    #pragma unroll
    for (int e = 0; e < 32; e++) {
        int idx = e*256 + tid;
        int o = idx >> 8, k = idx & 255;
        sUr[k*WPITCH + o] = Ur[(size_t)(ot*32 + o)*256 + k];
        sU [k*WPITCH + o] = U [(size_t)(ot*32 + o)*256 + k];
    }
    const float ub0 = Ub[ot*32 + o0];
    const float ub1 = Ub[ot*32 + o0 + 1];
    __syncthreads();

    for (int t = 0; t < 64; t++) {
        const float* Cin  = (t & 1) ? Cb : Ca;
        float*       Cout = (t & 1) ? Ca : Cb;

        float aU[4][2], aV[4][2];
        #pragma unroll
        for (int a = 0; a < 4; a++) { aU[a][0]=aU[a][1]=aV[a][0]=aV[a][1]=0.0f; }

        float pf[16];
        #pragma unroll
        for (int e = 0; e < 16; e++) {
            int idx = e*256 + tid;
            int c = idx >> 6, k = idx & 63;
            pf[e] = Cin[(size_t)(ct*64 + c)*256 + k];
        }

        for (int ch = 0; ch < 4; ch++) {
            #pragma unroll
            for (int e = 0; e < 16; e++) {
                int idx = e*256 + tid;
                int c = idx >> 6, k = idx & 63;
                sC[k*CPITCH + c] = pf[e];
            }
            __syncthreads();
            if (ch < 3) {
                #pragma unroll
                for (int e = 0; e < 16; e++) {
                    int idx = e*256 + tid;
                    int c = idx >> 6, k = idx & 63;
                    pf[e] = Cin[(size_t)(ct*64 + c)*256 + (ch+1)*64 + k];
                }
            }
            const float* wr = sUr + (size_t)ch*64*WPITCH + o0;
            const float* wu = sU  + (size_t)ch*64*WPITCH + o0;
            #pragma unroll 4
            for (int k = 0; k < 64; k++) {
                float4 cv  = *(const float4*)&sC[k*CPITCH + c0];
                float2 urv = *(const float2*)&wr[k*WPITCH];
                float2 uv  = *(const float2*)&wu[k*WPITCH];
                aU[0][0]+=cv.x*urv.x; aU[0][1]+=cv.x*urv.y; aV[0][0]+=cv.x*uv.x; aV[0][1]+=cv.x*uv.y;
                aU[1][0]+=cv.y*urv.x; aU[1][1]+=cv.y*urv.y; aV[1][0]+=cv.y*uv.x; aV[1][1]+=cv.y*uv.y;
                aU[2][0]+=cv.z*urv.x; aU[2][1]+=cv.z*urv.y; aV[2][0]+=cv.z*uv.x; aV[2][1]+=cv.z*uv.y;
                aU[3][0]+=cv.w*urv.x; aU[3][1]+=cv.w*urv.y; aV[3][0]+=cv.w*uv.x; aV[3][1]+=cv.w*uv.y;
            }
            __syncthreads();
        }

        const size_t trow = (size_t)(ct*64 + t) * 256;
        const int o_0 = ot*32 + o0;
        const float a1_0 = g_A1[trow + o_0];
        const float a1_1 = g_A1[trow + o_0 + 1];
        const float a2_0 = g_A2[trow + o_0];
        const float a2_1 = g_A2[trow + o_0 + 1];

        #pragma unroll
        for (int cc = 0; cc < 4; cc++) {
            int b = ct*64 + c0 + cc;
            float g = attn[b*64 + t];
            float ci0 = Cin[(size_t)b*256 + o_0];
            float ci1 = Cin[(size_t)b*256 + o_0 + 1];

            float u0 = aU[cc][0] + a1_0;
            float v0 = aV[cc][0] + ub0;
            float r0 = fast_sigmoid(u0);
            float h0 = fast_tanh(a2_0 + r0 * v0);
            Cout[(size_t)b*256 + o_0] = g*h0 + (1.0f - g)*ci0;

            float u1 = aU[cc][1] + a1_1;
            float v1 = aV[cc][1] + ub1;
            float r1 = fast_sigmoid(u1);
            float h1 = fast_tanh(a2_1 + r1 * v1);
            Cout[(size_t)b*256 + o_0 + 1] = g*h1 + (1.0f - g)*ci1;
        }

        if (t < 63) grid_barrier((unsigned)(t + 1));
    }
}

// ---------------------------------------------------------------------------
// next_mem = relu([prevM, C, questions] @ nm_w^T + nm_b).
// ---------------------------------------------------------------------------
__global__ void final_kernel(const float* __restrict__ prevM,
                             const float* __restrict__ questions,
                             const float* __restrict__ C,
                             const float* __restrict__ nmw,
                             const float* __restrict__ nmb,
                             float* __restrict__ out)
{
    __shared__ float sX[64*36];
    __shared__ float sW[64*68];
    const int rt = blockIdx.x;
    const int ot = blockIdx.y;
    const int tid = threadIdx.x;
    const int tr = tid & 7, to = tid >> 3;
    const int r0 = tr*4, o0 = to*2;

    float acc[4][2];
    #pragma unroll
    for (int a = 0; a < 4; a++) { acc[a][0]=acc[a][1]=0.0f; }

    for (int k0 = 0; k0 < 768; k0 += 64) {
        __syncthreads();
        #pragma unroll
        for (int e = 0; e < 8; e++) {
            int idx = e*256 + tid;
            int r = idx >> 6, k = idx & 63;
            int kg = k0 + k;
            const float* src; int off;
            if (kg < 256)      { src = prevM;     off = kg; }
            else if (kg < 512) { src = C;         off = kg - 256; }
            else               { src = questions; off = kg - 512; }
            sX[k*36 + r] = src[(size_t)(rt*32 + r)*256 + off];
        }
        #pragma unroll
        for (int e = 0; e < 16; e++) {
            int idx = e*256 + tid;
            int o = idx >> 6, k = idx & 63;
            sW[k*68 + o] = nmw[(size_t)(ot*64 + o)*768 + k0 + k];
        }
        __syncthreads();
        #pragma unroll 4
        for (int k = 0; k < 64; k++) {
            float4 xv = *(const float4*)&sX[k*36 + r0];
            float2 wv = *(const float2*)&sW[k*68 + o0];
            acc[0][0]+=xv.x*wv.x; acc[0][1]+=xv.x*wv.y;
            acc[1][0]+=xv.y*wv.x; acc[1][1]+=xv.y*wv.y;
            acc[2][0]+=xv.z*wv.x; acc[2][1]+=xv.z*wv.y;
            acc[3][0]+=xv.w*wv.x; acc[3][1]+=xv.w*wv.y;
        }
    }
    #pragma unroll
    for (int rr = 0; rr < 4; rr++)
        #pragma unroll
        for (int oo = 0; oo < 2; oo++) {
            int o = ot*64 + o0 + oo;
            float v = acc[rr][oo] + nmb[o];
            out[(size_t)(rt*32 + r0 + rr)*256 + o] = fmaxf(v, 0.0f);
        }
}

// ---------------------------------------------------------------------------
extern "C" void kernel_launch(void* const* d_in, const int* in_sizes, int n_in,
                              void* d_out, int out_size)
{
    const float* facts     = (const float*)d_in[0];
    const float* prevM     = (const float*)d_in[1];
    const float* questions = (const float*)d_in[2];
    const int*   doc_len   = (const int*)  d_in[3];
    const float* z1w = (const float*)d_in[4];
    const float* z1b = (const float*)d_in[5];
    const float* z2w = (const float*)d_in[6];
    const float* z2b = (const float*)d_in[7];
    const float* Wrw = (const float*)d_in[8];
    const float* Wrb = (const float*)d_in[9];
    const float* Urw = (const float*)d_in[10];
    const float* Urb = (const float*)d_in[11];
    const float* Ww  = (const float*)d_in[12];
    const float* Wb  = (const float*)d_in[13];
    const float* Uw  = (const float*)d_in[14];
    const float* Ub  = (const float*)d_in[15];
    const float* nmw = (const float*)d_in[16];
    const float* nmb = (const float*)d_in[17];

    float* out      = (float*)d_out;              // next_mem first
    float* out_attn = out + NM_ELEMS;             // attn second

    cudaFuncSetAttribute(gate_kernel,
                         cudaFuncAttributeMaxDynamicSharedMemorySize, GATE_SMEM_BYTES);
    const int gru_smem = GRU_SMEM_FLOATS * 4;
    cudaFuncSetAttribute(gru_persistent,
                         cudaFuncAttributeMaxDynamicSharedMemorySize, gru_smem);

    float *Ca, *Cb;
    cudaGetSymbolAddress((void**)&Ca, g_Ca);
    cudaGetSymbolAddress((void**)&Cb, g_Cb);

    zero_kernel<<<512, 512>>>();
    splitw_kernel<<<256, 256>>>(z1w);
    gate_kernel<<<512, 256, GATE_SMEM_BYTES>>>(facts, prevM, questions, z1b, z2w, z2b);
    softmax_kernel<<<256, 128>>>(doc_len, out_attn);
    a12_kernel<<<dim3(16, 8), 256>>>(facts, Wrw, Wrb, Urb, Ww, Wb);

    gru_persistent<<<STEP_CTAS, 256, gru_smem>>>(Ca, Cb, Urw, Uw, Ub, out_attn);

    // After t=63 (odd), final C lives in Ca
    final_kernel<<<dim3(32, 4), 256>>>(prevM, questions, Ca, nmw, nmb, out);
}

// round 6
// speedup vs baseline: 2.9466x; 1.0419x over previous
#include <cuda_runtime.h>
#include <cuda_bf16.h>
#include <math.h>
#include <math_constants.h>
#include <stdint.h>

// Problem dims
#define Nn 16
#define Ss 64
#define Hh 256
#define FAa 256
#define Bb (Nn*Ss)              // 1024 chains / rows
#define NM_ELEMS (Nn*Ss*Hh)     // 262144
#define ATTN_ELEMS (Nn*Ss*Ss)   // 65536

// Scratch (device globals: no allocation allowed)
__device__ float g_G [Bb*Ss];   // gate logits (n,i,j)
__device__ float g_A1[Bb*Hh];
__device__ float g_A2[Bb*Hh];
__device__ float g_Ca[Bb*Hh];
__device__ float g_Cb[Bb*Hh];
__device__ __nv_bfloat16 g_Whi[256*1024];   // z1w split hi
__device__ __nv_bfloat16 g_Wlo[256*1024];   // z1w split lo

__device__ unsigned g_bar_count;
__device__ unsigned g_bar_gen;

// ---------------------------------------------------------------------------
// Helpers
// ---------------------------------------------------------------------------
__device__ __forceinline__ float fast_tanh(float x)
{
    float e = __expf(2.0f * x);
    return 1.0f - __fdividef(2.0f, e + 1.0f);
}
__device__ __forceinline__ float fast_sigmoid(float x)
{
    float e = __expf(-x);
    return __fdividef(1.0f, 1.0f + e);
}

// ---- packed fp32x2 (B300 FFMA2) ----
__device__ __forceinline__ uint64_t packf2(float x)
{
    uint64_t r;
    uint32_t u = __float_as_uint(x);
    asm("mov.b64 %0, {%1, %1};" : "=l"(r) : "r"(u));
    return r;
}
__device__ __forceinline__ void fma2(uint64_t& d, uint64_t a, uint64_t b)
{
    asm("fma.rn.f32x2 %0, %1, %2, %0;" : "+l"(d) : "l"(a), "l"(b));
}
__device__ __forceinline__ float2 unpackf2(uint64_t v)
{
    float2 f;
    asm("mov.b64 {%0, %1}, %2;" : "=f"(f.x), "=f"(f.y) : "l"(v));
    return f;
}

// Pack two floats to bf16x2 (x -> low, y -> high) and return residual pack too.
__device__ __forceinline__ uint32_t split2(float x, float y, uint32_t& lo)
{
    uint32_t hi;
    asm("cvt.rn.bf16x2.f32 %0, %1, %2;" : "=r"(hi) : "f"(y), "f"(x));
    float xr = x - __uint_as_float(hi << 16);
    float yr = y - __uint_as_float(hi & 0xffff0000u);
    asm("cvt.rn.bf16x2.f32 %0, %1, %2;" : "=r"(lo) : "f"(yr), "f"(xr));
    return hi;
}

__device__ __forceinline__ void mma_bf16(float* d, const uint32_t* a,
                                         uint32_t b0, uint32_t b1)
{
    asm volatile(
        "mma.sync.aligned.m16n8k16.row.col.f32.bf16.bf16.f32 "
        "{%0,%1,%2,%3}, {%4,%5,%6,%7}, {%8,%9}, {%0,%1,%2,%3};"
        : "+f"(d[0]), "+f"(d[1]), "+f"(d[2]), "+f"(d[3])
        : "r"(a[0]), "r"(a[1]), "r"(a[2]), "r"(a[3]), "r"(b0), "r"(b1));
}

__device__ __forceinline__ void ldm_x4(uint32_t* r, uint32_t addr)
{
    asm volatile("ldmatrix.sync.aligned.m8n8.x4.shared.b16 {%0,%1,%2,%3}, [%4];"
        : "=r"(r[0]), "=r"(r[1]), "=r"(r[2]), "=r"(r[3]) : "r"(addr));
}

__device__ __forceinline__ void cp16(uint32_t dst, const void* src)
{
    asm volatile("cp.async.cg.shared.global [%0], [%1], 16;" :: "r"(dst), "l"(src));
}

// ---------------------------------------------------------------------------
// Zero initial GRU state + reset barrier
// ---------------------------------------------------------------------------
__global__ void zero_kernel() {
    int i = blockIdx.x * 512 + threadIdx.x;
    g_Ca[i] = 0.0f;
    if (i == 0) { g_bar_count = 0; g_bar_gen = 0; }
}

// ---------------------------------------------------------------------------
// Pre-split z1w into bf16 hi/lo
// ---------------------------------------------------------------------------
__global__ void splitw_kernel(const float* __restrict__ z1w) {
    int i = blockIdx.x * 256 + threadIdx.x;
    #pragma unroll
    for (int e = 0; e < 4; e++) {
        int idx = e * 65536 + i;
        float w = z1w[idx];
        __nv_bfloat16 h = __float2bfloat16_rn(w);
        g_Whi[idx] = h;
        g_Wlo[idx] = __float2bfloat16_rn(w - __bfloat162float(h));
    }
}

// ---------------------------------------------------------------------------
// Gate MLP via bf16-split mma.sync.m16n8k16 (unchanged from R5).
// ---------------------------------------------------------------------------
#define WOFF    0
#define WBUFSZ  73728
#define WHALF   36864
#define SFOFF   147456
#define QOFF    (SFOFF + 66048)
#define B1OFF   (QOFF + 4096)
#define Z2OFF   (B1OFF + 1024)
#define REDOFF  (Z2OFF + 1024)
#define GATE_SMEM_BYTES (REDOFF + 4096)

__global__ void __launch_bounds__(256, 1)
gate_kernel(const float* __restrict__ facts,
            const float* __restrict__ prevM,
            const float* __restrict__ questions,
            const float* __restrict__ z1b,
            const float* __restrict__ z2w,
            const float* __restrict__ z2b)
{
    extern __shared__ char smc[];
    float* sf  = (float*)(smc + SFOFF);
    float* sQ0 = (float*)(smc + QOFF);
    float* sQ1 = sQ0 + 256;
    float* sM0 = sQ1 + 256;
    float* sM1 = sM0 + 256;
    float* sb1 = (float*)(smc + B1OFF);
    float* sz2 = (float*)(smc + Z2OFF);
    float* red = (float*)(smc + REDOFF);
    const uint32_t smbase = (uint32_t)__cvta_generic_to_shared(smc);

    const int tid  = threadIdx.x;
    const int lane = tid & 31;
    const int wid  = tid >> 5;
    const int g    = lane >> 2;
    const int tg   = lane & 3;
    const int wm   = wid & 3;
    const int wn   = wid >> 2;

    const int bx  = blockIdx.x;
    const int n   = bx >> 5;
    const int ip  = bx & 31;
    const int ni0 = n*64 + ip*2;

    {
        const float2* f2 = (const float2*)(facts + (size_t)n * Ss * Hh);
        #pragma unroll
        for (int e = 0; e < 32; e++) {
            int idx = e*256 + tid;
            int j = idx >> 7, h2 = idx & 127;
            *(float2*)&sf[j*258 + h2*2] = f2[idx];
        }
        sQ0[tid] = questions[(size_t)ni0*256 + tid];
        sQ1[tid] = questions[(size_t)(ni0+1)*256 + tid];
        sM0[tid] = prevM[(size_t)ni0*256 + tid];
        sM1[tid] = prevM[(size_t)(ni0+1)*256 + tid];
        sb1[tid] = z1b[tid];
        sz2[tid] = z2w[tid];
    }

    {
        const char* gh = (const char*)(g_Whi + (size_t)tid*1024);
        const char* gl = (const char*)(g_Wlo + (size_t)tid*1024);
        uint32_t dh = smbase + WOFF + (uint32_t)tid*144;
        uint32_t dl = dh + WHALF;
        #pragma unroll
        for (int u = 0; u < 8; u++) { cp16(dh + u*16, gh + u*16); cp16(dl + u*16, gl + u*16); }
        asm volatile("cp.async.commit_group;");
        asm volatile("cp.async.wait_group 0;");
    }
    __syncthreads();

    float acc[2][16][4];
    #pragma unroll
    for (int mt = 0; mt < 2; mt++)
        #pragma unroll
        for (int nt = 0; nt < 16; nt++)
            #pragma unroll
            for (int v = 0; v < 4; v++) acc[mt][nt][v] = 0.0f;

    const uint32_t broff = (uint32_t)((wn*128 + ((lane>>4)&1)*8 + (lane&7)) * 144
                                      + ((lane>>3)&1)*16);

    for (int c = 0; c < 16; c++) {
        if (c < 15) {
            const char* gh = (const char*)(g_Whi + (size_t)tid*1024 + (c+1)*64);
            const char* gl = (const char*)(g_Wlo + (size_t)tid*1024 + (c+1)*64);
            uint32_t dh = smbase + WOFF + (uint32_t)(((c+1)&1)*WBUFSZ) + (uint32_t)tid*144;
            uint32_t dl = dh + WHALF;
            #pragma unroll
            for (int u = 0; u < 8; u++) { cp16(dh + u*16, gh + u*16); cp16(dl + u*16, gl + u*16); }
            asm volatile("cp.async.commit_group;");
        }

        const int  bterm = c >> 2;
        const int  h0    = (c & 3) * 64;
        const bool isabs = (bterm >= 2);
        const uint32_t wbase = smbase + WOFF + (uint32_t)((c&1)*WBUFSZ);

        #pragma unroll
        for (int ks = 0; ks < 4; ks++) {
            const int h = h0 + ks*16;

            uint32_t Ah[2][4], Al[2][4];
            #pragma unroll
            for (int mt = 0; mt < 2; mt++) {
                const int rb   = wm*32 + mt*16 + g;
                const int isel = rb >> 6;
                const float* tv = (bterm & 1) ? (isel ? sM1 : sM0)
                                              : (isel ? sQ1 : sQ0);
                const int j0 = rb & 63;
                const float* fr0 = &sf[j0*258 + h + tg*2];
                const float* fr1 = fr0 + 8*258;
                float2 t0  = *(const float2*)&tv[h + tg*2];
                float2 t1  = *(const float2*)&tv[h + tg*2 + 8];
                float2 fa  = *(const float2*)fr0;
                float2 fA  = *(const float2*)(fr0 + 8);
                float2 fb  = *(const float2*)fr1;
                float2 fB  = *(const float2*)(fr1 + 8);
                float z00, z01, z10, z11, z20, z21, z30, z31;
                if (isabs) {
                    z00 = fabsf(fa.x - t0.x); z01 = fabsf(fa.y - t0.y);
                    z10 = fabsf(fb.x - t0.x); z11 = fabsf(fb.y - t0.y);
                    z20 = fabsf(fA.x - t1.x); z21 = fabsf(fA.y - t1.y);
                    z30 = fabsf(fB.x - t1.x); z31 = fabsf(fB.y - t1.y);
                } else {
                    z00 = fa.x * t0.x; z01 = fa.y * t0.y;
                    z10 = fb.x * t0.x; z11 = fb.y * t0.y;
                    z20 = fA.x * t1.x; z21 = fA.y * t1.y;
                    z30 = fB.x * t1.x; z31 = fB.y * t1.y;
                }
                Ah[mt][0] = split2(z00, z01, Al[mt][0]);
                Ah[mt][1] = split2(z10, z11, Al[mt][1]);
                Ah[mt][2] = split2(z20, z21, Al[mt][2]);
                Ah[mt][3] = split2(z30, z31, Al[mt][3]);
            }

            #pragma unroll
            for (int p = 0; p < 8; p++) {
                uint32_t ah = wbase + broff + (uint32_t)(p*16*144 + ks*32);
                uint32_t bh[4], bl[4];
                ldm_x4(bh, ah);
                ldm_x4(bl, ah + WHALF);
                #pragma unroll
                for (int q2 = 0; q2 < 2; q2++) {
                    const int nt = p*2 + q2;
                    uint32_t b0h = bh[q2*2], b1h = bh[q2*2+1];
                    uint32_t b0l = bl[q2*2], b1l = bl[q2*2+1];
                    mma_bf16(acc[0][nt], Ah[0], b0h, b1h);
                    mma_bf16(acc[1][nt], Ah[1], b0h, b1h);
                    mma_bf16(acc[0][nt], Al[0], b0h, b1h);
                    mma_bf16(acc[1][nt], Al[1], b0h, b1h);
                    mma_bf16(acc[0][nt], Ah[0], b0l, b1l);
                    mma_bf16(acc[1][nt], Ah[1], b0l, b1l);
                }
            }
        }

        if (c < 15) asm volatile("cp.async.wait_group 0;");
        __syncthreads();
    }

    #pragma unroll
    for (int mt = 0; mt < 2; mt++) {
        #pragma unroll
        for (int rh = 0; rh < 2; rh++) {
            const int r = wm*32 + mt*16 + rh*8 + g;
            float s = 0.0f;
            #pragma unroll
            for (int nt = 0; nt < 16; nt++) {
                #pragma unroll
                for (int cc = 0; cc < 2; cc++) {
                    const int a = wn*128 + nt*8 + tg*2 + cc;
                    float x = acc[mt][nt][rh*2 + cc] + sb1[a];
                    s += fast_tanh(x) * sz2[a];
                }
            }
            red[r*8 + wn*4 + tg] = s;
        }
    }
    __syncthreads();
    if (tid < 128) {
        float G = z2b[0];
        #pragma unroll
        for (int u = 0; u < 8; u++) G += red[tid*8 + u];
        const int isel = tid >> 6, j = tid & 63;
        g_G[(ni0 + isel)*64 + j] = G;
    }
}

// ---------------------------------------------------------------------------
// Masked softmax over facts axis j. One warp per (n,i) row.
// ---------------------------------------------------------------------------
__global__ void softmax_kernel(const int* __restrict__ doc_len,
                               float* __restrict__ out_attn)
{
    int row  = blockIdx.x * 4 + (threadIdx.x >> 5);
    int lane = threadIdx.x & 31;
    int n  = row >> 6;
    int dl = doc_len[n];

    float v0 = g_G[row*64 + lane];
    float v1 = g_G[row*64 + 32 + lane];
    float x0 = (lane      < dl && v0 != 0.0f) ? v0 : -CUDART_INF_F;
    float x1 = (lane + 32 < dl && v1 != 0.0f) ? v1 : -CUDART_INF_F;

    float mx = fmaxf(x0, x1);
    #pragma unroll
    for (int o = 16; o >= 1; o >>= 1)
        mx = fmaxf(mx, __shfl_xor_sync(0xffffffffu, mx, o));

    float e0 = expf(x0 - mx);
    float e1 = expf(x1 - mx);
    float s = e0 + e1;
    #pragma unroll
    for (int o = 16; o >= 1; o >>= 1)
        s += __shfl_xor_sync(0xffffffffu, s, o);

    float inv = 1.0f / s;
    out_attn[row*64 + lane]      = e0 * inv;
    out_attn[row*64 + 32 + lane] = e1 * inv;
}

// ---------------------------------------------------------------------------
// A1 = facts@Wr^T + Wr_b + Ur_b ; A2 = facts@W^T + W_b   (fp32x2 FFMA2)
// ---------------------------------------------------------------------------
__global__ void a12_kernel(const float* __restrict__ facts,
                           const float* __restrict__ Wr, const float* __restrict__ Wrb,
                           const float* __restrict__ Urb,
                           const float* __restrict__ W,  const float* __restrict__ Wb)
{
    __shared__ float sX[64*68];
    __shared__ float sWm[64*68];
    const int rt = blockIdx.x;
    const int yy = blockIdx.y;
    const bool first = (yy < 4);
    const int ot = first ? yy : yy - 4;
    const float* Wm = first ? Wr : W;
    float* outp = first ? g_A1 : g_A2;

    const int tid = threadIdx.x;
    const int tr = tid & 15, to = tid >> 4;
    const int r0 = tr*4, o0 = to*4;
    uint64_t accp[4][2];
    #pragma unroll
    for (int a = 0; a < 4; a++) { accp[a][0] = 0ull; accp[a][1] = 0ull; }

    for (int k0 = 0; k0 < 256; k0 += 64) {
        __syncthreads();
        #pragma unroll
        for (int e = 0; e < 16; e++) {
            int idx = e*256 + tid;
            int r = idx >> 6, k = idx & 63;
            sX[k*68 + r]  = facts[(size_t)(rt*64 + r)*256 + k0 + k];
            int o = r;
            sWm[k*68 + o] = Wm[(size_t)(ot*64 + o)*256 + k0 + k];
        }
        __syncthreads();
        #pragma unroll 4
        for (int k = 0; k < 64; k++) {
            float4 xv = *(const float4*)&sX[k*68 + r0];
            uint64_t w01 = *(const uint64_t*)&sWm[k*68 + o0];
            uint64_t w23 = *(const uint64_t*)&sWm[k*68 + o0 + 2];
            uint64_t p0 = packf2(xv.x), p1 = packf2(xv.y);
            uint64_t p2 = packf2(xv.z), p3 = packf2(xv.w);
            fma2(accp[0][0], p0, w01); fma2(accp[0][1], p0, w23);
            fma2(accp[1][0], p1, w01); fma2(accp[1][1], p1, w23);
            fma2(accp[2][0], p2, w01); fma2(accp[2][1], p2, w23);
            fma2(accp[3][0], p3, w01); fma2(accp[3][1], p3, w23);
        }
    }
    #pragma unroll
    for (int rr = 0; rr < 4; rr++) {
        float2 lo = unpackf2(accp[rr][0]);
        float2 hi = unpackf2(accp[rr][1]);
        float vals[4] = {lo.x, lo.y, hi.x, hi.y};
        #pragma unroll
        for (int oo = 0; oo < 4; oo++) {
            int o = ot*64 + o0 + oo;
            float bias = first ? (Wrb[o] + Urb[o]) : Wb[o];
            outp[(size_t)(rt*64 + r0 + rr)*256 + o] = vals[oo] + bias;
        }
    }
}

// ---------------------------------------------------------------------------
// Persistent GRU with fp32x2 FFMA2. 128 CTAs, each (64-chain x 32-out) tile.
// Thread = 2 chains x 4 outs.
// ---------------------------------------------------------------------------
#define STEP_CTAS 128
#define WPITCH 34
#define CPITCH 68
#define GRU_SMEM_FLOATS (2*256*WPITCH + 64*CPITCH)

__device__ __forceinline__ void grid_barrier(unsigned expect)
{
    __syncthreads();
    if (threadIdx.x == 0) {
        __threadfence();
        unsigned old = atomicAdd(&g_bar_count, 1);
        if (old == STEP_CTAS - 1) {
            g_bar_count = 0;
            asm volatile("st.release.gpu.u32 [%0], %1;"
                         :: "l"(&g_bar_gen), "r"(expect) : "memory");
        } else {
            unsigned v;
            do {
                asm volatile("ld.acquire.gpu.u32 %0, [%1];"
                             : "=r"(v) : "l"(&g_bar_gen) : "memory");
            } while (v < expect);
        }
    }
    __syncthreads();
}

__global__ void __launch_bounds__(256, 1)
gru_persistent(float* __restrict__ Ca, float* __restrict__ Cb,
               const float* __restrict__ Ur, const float* __restrict__ U,
               const float* __restrict__ Ub,
               const float* __restrict__ attn)
{
    extern __shared__ float smem[];
    float* sUr = smem;
    float* sU  = sUr + 256*WPITCH;
    float* sC  = sU  + 256*WPITCH;

    const int bx  = blockIdx.x;
    const int ct  = bx >> 3;
    const int ot  = bx & 7;
    const int tid = threadIdx.x;
    const int c0  = (tid & 31) * 2;     // 2 chains
    const int o0  = (tid >> 5) * 4;     // 4 outs

    #pragma unroll
    for (int e = 0; e < 32; e++) {
        int idx = e*256 + tid;
        int o = idx >> 8, k = idx & 255;
        sUr[k*WPITCH + o] = Ur[(size_t)(ot*32 + o)*256 + k];
        sU [k*WPITCH + o] = U [(size_t)(ot*32 + o)*256 + k];
    }
    const int o_0 = ot*32 + o0;
    const float4 ubv = *(const float4*)&Ub[o_0];
    __syncthreads();

    for (int t = 0; t < 64; t++) {
        const float* Cin  = (t & 1) ? Cb : Ca;
        float*       Cout = (t & 1) ? Ca : Cb;

        uint64_t aU[2][2], aV[2][2];
        #pragma unroll
        for (int a = 0; a < 2; a++) {
            aU[a][0]=0ull; aU[a][1]=0ull; aV[a][0]=0ull; aV[a][1]=0ull;
        }

        float pf[16];
        #pragma unroll
        for (int e = 0; e < 16; e++) {
            int idx = e*256 + tid;
            int c = idx >> 6, k = idx & 63;
            pf[e] = Cin[(size_t)(ct*64 + c)*256 + k];
        }

        for (int ch = 0; ch < 4; ch++) {
            #pragma unroll
            for (int e = 0; e < 16; e++) {
                int idx = e*256 + tid;
                int c = idx >> 6, k = idx & 63;
                sC[k*CPITCH + c] = pf[e];
            }
            __syncthreads();
            if (ch < 3) {
                #pragma unroll
                for (int e = 0; e < 16; e++) {
                    int idx = e*256 + tid;
                    int c = idx >> 6, k = idx & 63;
                    pf[e] = Cin[(size_t)(ct*64 + c)*256 + (ch+1)*64 + k];
                }
            }
            const float* wr = sUr + (size_t)ch*64*WPITCH + o0;
            const float* wu = sU  + (size_t)ch*64*WPITCH + o0;
            #pragma unroll 4
            for (int k = 0; k < 64; k++) {
                float2 cv = *(const float2*)&sC[k*CPITCH + c0];
                uint64_t ur01 = *(const uint64_t*)&wr[k*WPITCH];
                uint64_t ur23 = *(const uint64_t*)&wr[k*WPITCH + 2];
                uint64_t u01  = *(const uint64_t*)&wu[k*WPITCH];
                uint64_t u23  = *(const uint64_t*)&wu[k*WPITCH + 2];
                uint64_t cp0 = packf2(cv.x);
                uint64_t cp1 = packf2(cv.y);
                fma2(aU[0][0], cp0, ur01); fma2(aU[0][1], cp0, ur23);
                fma2(aU[1][0], cp1, ur01); fma2(aU[1][1], cp1, ur23);
                fma2(aV[0][0], cp0, u01);  fma2(aV[0][1], cp0, u23);
                fma2(aV[1][0], cp1, u01);  fma2(aV[1][1], cp1, u23);
            }
            __syncthreads();
        }

        const size_t trow = (size_t)(ct*64 + t) * 256;
        const float4 a1v = *(const float4*)&g_A1[trow + o_0];
        const float4 a2v = *(const float4*)&g_A2[trow + o_0];

        #pragma unroll
        for (int cc = 0; cc < 2; cc++) {
            int b = ct*64 + c0 + cc;
            float g = attn[b*64 + t];
            float4 ci = *(const float4*)&Cin[(size_t)b*256 + o_0];
            float2 su01 = unpackf2(aU[cc][0]);
            float2 su23 = unpackf2(aU[cc][1]);
            float2 sv01 = unpackf2(aV[cc][0]);
            float2 sv23 = unpackf2(aV[cc][1]);

            float4 res;
            {
                float r = fast_sigmoid(su01.x + a1v.x);
                float h = fast_tanh(a2v.x + r * (sv01.x + ubv.x));
                res.x = g*h + (1.0f - g)*ci.x;
            }
            {
                float r = fast_sigmoid(su01.y + a1v.y);
                float h = fast_tanh(a2v.y + r * (sv01.y + ubv.y));
                res.y = g*h + (1.0f - g)*ci.y;
            }
            {
                float r = fast_sigmoid(su23.x + a1v.z);
                float h = fast_tanh(a2v.z + r * (sv23.x + ubv.z));
                res.z = g*h + (1.0f - g)*ci.z;
            }
            {
                float r = fast_sigmoid(su23.y + a1v.w);
                float h = fast_tanh(a2v.w + r * (sv23.y + ubv.w));
                res.w = g*h + (1.0f - g)*ci.w;
            }
            *(float4*)&Cout[(size_t)b*256 + o_0] = res;
        }

        if (t < 63) grid_barrier((unsigned)(t + 1));
    }
}

// ---------------------------------------------------------------------------
// next_mem = relu([prevM, C, questions] @ nm_w^T + nm_b).
// ---------------------------------------------------------------------------
__global__ void final_kernel(const float* __restrict__ prevM,
                             const float* __restrict__ questions,
                             const float* __restrict__ C,
                             const float* __restrict__ nmw,
                             const float* __restrict__ nmb,
                             float* __restrict__ out)
{
    __shared__ float sX[64*36];
    __shared__ float sW[64*68];
    const int rt = blockIdx.x;
    const int ot = blockIdx.y;
    const int tid = threadIdx.x;
    const int tr = tid & 7, to = tid >> 3;
    const int r0 = tr*4, o0 = to*2;

    float acc[4][2];
    #pragma unroll
    for (int a = 0; a < 4; a++) { acc[a][0]=acc[a][1]=0.0f; }

    for (int k0 = 0; k0 < 768; k0 += 64) {
        __syncthreads();
        #pragma unroll
        for (int e = 0; e < 8; e++) {
            int idx = e*256 + tid;
            int r = idx >> 6, k = idx & 63;
            int kg = k0 + k;
            const float* src; int off;
            if (kg < 256)      { src = prevM;     off = kg; }
            else if (kg < 512) { src = C;         off = kg - 256; }
            else               { src = questions; off = kg - 512; }
            sX[k*36 + r] = src[(size_t)(rt*32 + r)*256 + off];
        }
        #pragma unroll
        for (int e = 0; e < 16; e++) {
            int idx = e*256 + tid;
            int o = idx >> 6, k = idx & 63;
            sW[k*68 + o] = nmw[(size_t)(ot*64 + o)*768 + k0 + k];
        }
        __syncthreads();
        #pragma unroll 4
        for (int k = 0; k < 64; k++) {
            float4 xv = *(const float4*)&sX[k*36 + r0];
            float2 wv = *(const float2*)&sW[k*68 + o0];
            acc[0][0]+=xv.x*wv.x; acc[0][1]+=xv.x*wv.y;
            acc[1][0]+=xv.y*wv.x; acc[1][1]+=xv.y*wv.y;
            acc[2][0]+=xv.z*wv.x; acc[2][1]+=xv.z*wv.y;
            acc[3][0]+=xv.w*wv.x; acc[3][1]+=xv.w*wv.y;
        }
    }
    #pragma unroll
    for (int rr = 0; rr < 4; rr++)
        #pragma unroll
        for (int oo = 0; oo < 2; oo++) {
            int o = ot*64 + o0 + oo;
            float v = acc[rr][oo] + nmb[o];
            out[(size_t)(rt*32 + r0 + rr)*256 + o] = fmaxf(v, 0.0f);
        }
}

// ---------------------------------------------------------------------------
extern "C" void kernel_launch(void* const* d_in, const int* in_sizes, int n_in,
                              void* d_out, int out_size)
{
    const float* facts     = (const float*)d_in[0];
    const float* prevM     = (const float*)d_in[1];
    const float* questions = (const float*)d_in[2];
    const int*   doc_len   = (const int*)  d_in[3];
    const float* z1w = (const float*)d_in[4];
    const float* z1b = (const float*)d_in[5];
    const float* z2w = (const float*)d_in[6];
    const float* z2b = (const float*)d_in[7];
    const float* Wrw = (const float*)d_in[8];
    const float* Wrb = (const float*)d_in[9];
    const float* Urw = (const float*)d_in[10];
    const float* Urb = (const float*)d_in[11];
    const float* Ww  = (const float*)d_in[12];
    const float* Wb  = (const float*)d_in[13];
    const float* Uw  = (const float*)d_in[14];
    const float* Ub  = (const float*)d_in[15];
    const float* nmw = (const float*)d_in[16];
    const float* nmb = (const float*)d_in[17];

    float* out      = (float*)d_out;              // next_mem first
    float* out_attn = out + NM_ELEMS;             // attn second

    cudaFuncSetAttribute(gate_kernel,
                         cudaFuncAttributeMaxDynamicSharedMemorySize, GATE_SMEM_BYTES);
    const int gru_smem = GRU_SMEM_FLOATS * 4;
    cudaFuncSetAttribute(gru_persistent,
                         cudaFuncAttributeMaxDynamicSharedMemorySize, gru_smem);

    float *Ca, *Cb;
    cudaGetSymbolAddress((void**)&Ca, g_Ca);
    cudaGetSymbolAddress((void**)&Cb, g_Cb);

    zero_kernel<<<512, 512>>>();
    splitw_kernel<<<256, 256>>>(z1w);
    gate_kernel<<<512, 256, GATE_SMEM_BYTES>>>(facts, prevM, questions, z1b, z2w, z2b);
    softmax_kernel<<<256, 128>>>(doc_len, out_attn);
    a12_kernel<<<dim3(16, 8), 256>>>(facts, Wrw, Wrb, Urb, Ww, Wb);

    gru_persistent<<<STEP_CTAS, 256, gru_smem>>>(Ca, Cb, Urw, Uw, Ub, out_attn);

    // After t=63 (odd), final C lives in Ca
    final_kernel<<<dim3(32, 4), 256>>>(prevM, questions, Ca, nmw, nmb, out);
}